// round 1
// baseline (speedup 1.0000x reference)
#include <cuda_runtime.h>
#include <cuda_bf16.h>
#include <math.h>
#include <stdint.h>

// Problem constants
#define BB 2
#define TT 2048
#define DIM 4096
#define NH 32
#define NKV 8
#define HD 128

// Scratch (device globals; no allocation allowed)
__device__ float g_q[(size_t)BB * TT * NH * HD];    // 64 MB
__device__ float g_k[(size_t)BB * TT * NKV * HD];   // 16 MB
__device__ float g_v[(size_t)BB * TT * NKV * HD];   // 16 MB
__device__ float g_ctx[(size_t)BB * TT * NH * HD];  // 64 MB

// ---------------------------------------------------------------------------
// SGEMM: C[M,N] = A[M,K] @ W[N,K]^T   (both row-major, K multiple of 8,
// M,N multiples of 128). 256 threads, 128x128x8 tile, 8x8 per thread.
// ---------------------------------------------------------------------------
__global__ __launch_bounds__(256) void sgemm_nt(const float* __restrict__ A,
                                                const float* __restrict__ W,
                                                float* __restrict__ C,
                                                int M, int N, int K) {
    __shared__ float As[8][132];
    __shared__ float Ws[8][132];

    const int bn = blockIdx.x * 128;
    const int bm = blockIdx.y * 128;
    const int tid = threadIdx.x;
    const int ty = tid >> 4;   // 0..15
    const int tx = tid & 15;   // 0..15

    const int lrow = tid >> 1;         // 0..127
    const int lkk  = (tid & 1) * 4;    // 0 or 4

    float acc[8][8];
#pragma unroll
    for (int i = 0; i < 8; i++)
#pragma unroll
        for (int j = 0; j < 8; j++) acc[i][j] = 0.f;

    const float* Arow = A + (size_t)(bm + lrow) * K + lkk;
    const float* Wrow = W + (size_t)(bn + lrow) * K + lkk;

    for (int k0 = 0; k0 < K; k0 += 8) {
        float4 a = *(const float4*)(Arow + k0);
        float4 w = *(const float4*)(Wrow + k0);
        As[lkk + 0][lrow] = a.x; As[lkk + 1][lrow] = a.y;
        As[lkk + 2][lrow] = a.z; As[lkk + 3][lrow] = a.w;
        Ws[lkk + 0][lrow] = w.x; Ws[lkk + 1][lrow] = w.y;
        Ws[lkk + 2][lrow] = w.z; Ws[lkk + 3][lrow] = w.w;
        __syncthreads();

#pragma unroll
        for (int kk = 0; kk < 8; kk++) {
            float ar[8], br[8];
            float4 a0 = *(const float4*)(&As[kk][ty * 8]);
            float4 a1 = *(const float4*)(&As[kk][ty * 8 + 4]);
            float4 b0 = *(const float4*)(&Ws[kk][tx * 8]);
            float4 b1 = *(const float4*)(&Ws[kk][tx * 8 + 4]);
            ar[0]=a0.x; ar[1]=a0.y; ar[2]=a0.z; ar[3]=a0.w;
            ar[4]=a1.x; ar[5]=a1.y; ar[6]=a1.z; ar[7]=a1.w;
            br[0]=b0.x; br[1]=b0.y; br[2]=b0.z; br[3]=b0.w;
            br[4]=b1.x; br[5]=b1.y; br[6]=b1.z; br[7]=b1.w;
#pragma unroll
            for (int i = 0; i < 8; i++)
#pragma unroll
                for (int j = 0; j < 8; j++)
                    acc[i][j] += ar[i] * br[j];
        }
        __syncthreads();
    }

#pragma unroll
    for (int i = 0; i < 8; i++) {
        float* crow = C + (size_t)(bm + ty * 8 + i) * N + bn + tx * 8;
        float4 c0 = make_float4(acc[i][0], acc[i][1], acc[i][2], acc[i][3]);
        float4 c1 = make_float4(acc[i][4], acc[i][5], acc[i][6], acc[i][7]);
        *(float4*)(crow) = c0;
        *(float4*)(crow + 4) = c1;
    }
}

// ---------------------------------------------------------------------------
// RoPE on g_q and g_k in place. One thread per (even,odd) pair.
// ---------------------------------------------------------------------------
__global__ void rope_kernel(const float* __restrict__ fc, const float* __restrict__ fs) {
    const int NQ = BB * TT * NH * (HD / 2);
    const int NK = BB * TT * NKV * (HD / 2);
    int i = blockIdx.x * blockDim.x + threadIdx.x;
    if (i < NQ) {
        int di = i & 63;
        int h  = (i >> 6) & 31;
        int t  = (i >> 11) & 2047;
        int b  = i >> 22;
        size_t base = (((size_t)(b * TT + t) * NH + h) << 7) + 2 * di;
        float c = fc[t * 64 + di], s = fs[t * 64 + di];
        float xr = g_q[base], xi = g_q[base + 1];
        g_q[base]     = xr * c - xi * s;
        g_q[base + 1] = xr * s + xi * c;
    } else if (i < NQ + NK) {
        int j = i - NQ;
        int di = j & 63;
        int h  = (j >> 6) & 7;
        int t  = (j >> 9) & 2047;
        int b  = j >> 20;
        size_t base = (((size_t)(b * TT + t) * NKV + h) << 7) + 2 * di;
        float c = fc[t * 64 + di], s = fs[t * 64 + di];
        float xr = g_k[base], xi = g_k[base + 1];
        g_k[base]     = xr * c - xi * s;
        g_k[base + 1] = xr * s + xi * c;
    }
}

// ---------------------------------------------------------------------------
// Flash attention (non-causal, full 2048 keys). fp32.
// Block: one (b, h, 64-row q tile). 256 threads = (ry 0..15) x (cx 0..15).
// Each thread: 4 q rows (ry + 16*rr), 8 output cols (cx*8..cx*8+7),
// scores for cols j = cx + 16*jj.
// ---------------------------------------------------------------------------
#define QSTR 132
#define PSTR 68
__global__ __launch_bounds__(256) void flash_kernel() {
    extern __shared__ float smem[];
    float* sq = smem;                    // [64][132]
    float* sk = sq + 64 * QSTR;          // [64][132]
    float* sv = sk + 64 * QSTR;          // [64][132]
    float* sp = sv + 64 * QSTR;          // [64][68]

    const int tid = threadIdx.x;
    const int ry = tid >> 4;
    const int cx = tid & 15;
    const int q0 = blockIdx.x * 64;
    const int h  = blockIdx.y;
    const int b  = blockIdx.z;
    const int kh = h & 7;

    // load q tile
    {
        const size_t qbase = ((size_t)(b * TT + q0) * NH + h) << 7;
        for (int i = tid; i < 64 * 32; i += 256) {
            int row = i >> 5, d4 = (i & 31) << 2;
            *(float4*)(sq + row * QSTR + d4) =
                *(const float4*)(g_q + qbase + (size_t)row * (NH * HD) + d4);
        }
    }

    float o[4][8];
    float m[4], l[4];
#pragma unroll
    for (int r = 0; r < 4; r++) {
        m[r] = -1e30f; l[r] = 0.f;
#pragma unroll
        for (int c = 0; c < 8; c++) o[r][c] = 0.f;
    }
    const float scale = 0.08838834764831845f; // 1/sqrt(128)

    for (int s0 = 0; s0 < TT; s0 += 64) {
        __syncthreads();
        // load k, v tiles
        {
            const size_t kbase = ((size_t)(b * TT + s0) * NKV + kh) << 7;
            for (int i = tid; i < 64 * 32; i += 256) {
                int row = i >> 5, d4 = (i & 31) << 2;
                size_t g = kbase + (size_t)row * (NKV * HD) + d4;
                *(float4*)(sk + row * QSTR + d4) = *(const float4*)(g_k + g);
                *(float4*)(sv + row * QSTR + d4) = *(const float4*)(g_v + g);
            }
        }
        __syncthreads();

        // scores
        float sc[4][4];
#pragma unroll
        for (int rr = 0; rr < 4; rr++)
#pragma unroll
            for (int jj = 0; jj < 4; jj++) sc[rr][jj] = 0.f;

        for (int d = 0; d < HD; d += 4) {
            float4 qv[4], kv[4];
#pragma unroll
            for (int rr = 0; rr < 4; rr++)
                qv[rr] = *(const float4*)(sq + (ry + 16 * rr) * QSTR + d);
#pragma unroll
            for (int jj = 0; jj < 4; jj++)
                kv[jj] = *(const float4*)(sk + (cx + 16 * jj) * QSTR + d);
#pragma unroll
            for (int rr = 0; rr < 4; rr++)
#pragma unroll
                for (int jj = 0; jj < 4; jj++)
                    sc[rr][jj] += qv[rr].x * kv[jj].x + qv[rr].y * kv[jj].y +
                                  qv[rr].z * kv[jj].z + qv[rr].w * kv[jj].w;
        }

        // online softmax per row
#pragma unroll
        for (int rr = 0; rr < 4; rr++) {
#pragma unroll
            for (int jj = 0; jj < 4; jj++) sc[rr][jj] *= scale;
            float mt = sc[rr][0];
#pragma unroll
            for (int jj = 1; jj < 4; jj++) mt = fmaxf(mt, sc[rr][jj]);
#pragma unroll
            for (int off = 8; off > 0; off >>= 1)
                mt = fmaxf(mt, __shfl_xor_sync(0xffffffffu, mt, off));
            float mnew = fmaxf(m[rr], mt);
            float alpha = __expf(m[rr] - mnew);
            float ls = 0.f;
#pragma unroll
            for (int jj = 0; jj < 4; jj++) {
                sc[rr][jj] = __expf(sc[rr][jj] - mnew);
                ls += sc[rr][jj];
            }
#pragma unroll
            for (int off = 8; off > 0; off >>= 1)
                ls += __shfl_xor_sync(0xffffffffu, ls, off);
            l[rr] = l[rr] * alpha + ls;
            m[rr] = mnew;
#pragma unroll
            for (int jj = 0; jj < 4; jj++)
                sp[(ry + 16 * rr) * PSTR + cx + 16 * jj] = sc[rr][jj];
#pragma unroll
            for (int c = 0; c < 8; c++) o[rr][c] *= alpha;
        }
        __syncthreads();

        // PV accumulate
        for (int s = 0; s < 64; s++) {
            float p[4];
#pragma unroll
            for (int rr = 0; rr < 4; rr++)
                p[rr] = sp[(ry + 16 * rr) * PSTR + s];
            float4 v0 = *(const float4*)(sv + s * QSTR + cx * 8);
            float4 v1 = *(const float4*)(sv + s * QSTR + cx * 8 + 4);
#pragma unroll
            for (int rr = 0; rr < 4; rr++) {
                o[rr][0] += p[rr] * v0.x; o[rr][1] += p[rr] * v0.y;
                o[rr][2] += p[rr] * v0.z; o[rr][3] += p[rr] * v0.w;
                o[rr][4] += p[rr] * v1.x; o[rr][5] += p[rr] * v1.y;
                o[rr][6] += p[rr] * v1.z; o[rr][7] += p[rr] * v1.w;
            }
        }
    }

    // epilogue: normalize and store ctx[b, t, h, d]
#pragma unroll
    for (int rr = 0; rr < 4; rr++) {
        float inv = 1.0f / l[rr];
        int t = q0 + ry + 16 * rr;
        size_t base = (((size_t)(b * TT + t) * NH + h) << 7) + cx * 8;
        float4 c0 = make_float4(o[rr][0] * inv, o[rr][1] * inv,
                                o[rr][2] * inv, o[rr][3] * inv);
        float4 c1 = make_float4(o[rr][4] * inv, o[rr][5] * inv,
                                o[rr][6] * inv, o[rr][7] * inv);
        *(float4*)(g_ctx + base) = c0;
        *(float4*)(g_ctx + base + 4) = c1;
    }
}

// ---------------------------------------------------------------------------
extern "C" void kernel_launch(void* const* d_in, const int* in_sizes, int n_in,
                              void* d_out, int out_size) {
    const float* x  = (const float*)d_in[0];
    const float* wq = (const float*)d_in[1];
    const float* wk = (const float*)d_in[2];
    const float* wv = (const float*)d_in[3];
    const float* wo = (const float*)d_in[4];
    const float* fc = (const float*)d_in[5];
    const float* fs = (const float*)d_in[6];
    float* out = (float*)d_out;

    float *qp, *kp, *vp, *ctxp;
    cudaGetSymbolAddress((void**)&qp,   g_q);
    cudaGetSymbolAddress((void**)&kp,   g_k);
    cudaGetSymbolAddress((void**)&vp,   g_v);
    cudaGetSymbolAddress((void**)&ctxp, g_ctx);

    const int M = BB * TT;  // 4096

    // Projections
    sgemm_nt<<<dim3(DIM / 128, M / 128), 256>>>(x, wq, qp, M, DIM, DIM);
    sgemm_nt<<<dim3((NKV * HD) / 128, M / 128), 256>>>(x, wk, kp, M, NKV * HD, DIM);
    sgemm_nt<<<dim3((NKV * HD) / 128, M / 128), 256>>>(x, wv, vp, M, NKV * HD, DIM);

    // RoPE
    {
        int total = BB * TT * (NH + NKV) * (HD / 2);
        rope_kernel<<<(total + 255) / 256, 256>>>(fc, fs);
    }

    // Flash attention
    {
        size_t shmem = (3 * 64 * QSTR + 64 * PSTR) * sizeof(float);
        cudaFuncSetAttribute(flash_kernel,
                             cudaFuncAttributeMaxDynamicSharedMemorySize,
                             (int)shmem);
        flash_kernel<<<dim3(TT / 64, NH, BB), 256, shmem>>>();
    }

    // Output projection
    sgemm_nt<<<dim3(DIM / 128, M / 128), 256>>>(ctxp, wo, out, M, DIM, DIM);
}

// round 3
// speedup vs baseline: 1.7852x; 1.7852x over previous
#include <cuda_runtime.h>
#include <cuda_bf16.h>
#include <math.h>
#include <stdint.h>

#define BB 2
#define TT 2048
#define DIM 4096
#define NH 32
#define NKV 8
#define HD 128
#define MTOK (BB * TT)   // 4096 token rows
#define GK 4096

// ---------------- device scratch (no allocation allowed) -------------------
__device__ __align__(16) float g_q[(size_t)MTOK * NH * HD];
__device__ __align__(16) float g_k[(size_t)MTOK * NKV * HD];
__device__ __align__(16) float g_v[(size_t)MTOK * NKV * HD];
__device__ __align__(16) float g_ctx[(size_t)MTOK * DIM];

__device__ __align__(16) __nv_bfloat16 g_xh[(size_t)MTOK * DIM];
__device__ __align__(16) __nv_bfloat16 g_xl[(size_t)MTOK * DIM];
__device__ __align__(16) __nv_bfloat16 g_wqh[(size_t)DIM * DIM];
__device__ __align__(16) __nv_bfloat16 g_wql[(size_t)DIM * DIM];
__device__ __align__(16) __nv_bfloat16 g_wkh[(size_t)NKV * HD * DIM];
__device__ __align__(16) __nv_bfloat16 g_wkl[(size_t)NKV * HD * DIM];
__device__ __align__(16) __nv_bfloat16 g_wvh[(size_t)NKV * HD * DIM];
__device__ __align__(16) __nv_bfloat16 g_wvl[(size_t)NKV * HD * DIM];
__device__ __align__(16) __nv_bfloat16 g_woh[(size_t)DIM * DIM];
__device__ __align__(16) __nv_bfloat16 g_wol[(size_t)DIM * DIM];
__device__ __align__(16) __nv_bfloat16 g_ch[(size_t)MTOK * DIM];
__device__ __align__(16) __nv_bfloat16 g_cl[(size_t)MTOK * DIM];

// ---------------- helpers ----------------------------------------------
__device__ __forceinline__ uint32_t smem_u32(const void* p) {
    uint32_t a;
    asm("{ .reg .u64 t; cvta.to.shared.u64 t, %1; cvt.u32.u64 %0, t; }"
        : "=r"(a) : "l"(p));
    return a;
}
__device__ __forceinline__ void cpa16(uint32_t dst, const void* src) {
    asm volatile("cp.async.cg.shared.global [%0], [%1], 16;"
                 :: "r"(dst), "l"(src) : "memory");
}
__device__ __forceinline__ void cp_commit() {
    asm volatile("cp.async.commit_group;" ::: "memory");
}
__device__ __forceinline__ void cp_wait1() {
    asm volatile("cp.async.wait_group 1;" ::: "memory");
}
__device__ __forceinline__ void cp_wait0() {
    asm volatile("cp.async.wait_group 0;" ::: "memory");
}
__device__ __forceinline__ void ldsm4(uint32_t* r, uint32_t addr) {
    asm volatile("ldmatrix.sync.aligned.m8n8.x4.shared.b16 {%0,%1,%2,%3}, [%4];"
                 : "=r"(r[0]), "=r"(r[1]), "=r"(r[2]), "=r"(r[3]) : "r"(addr));
}
__device__ __forceinline__ void mma16816(float* d, const uint32_t* a, const uint32_t* b) {
    asm volatile(
        "mma.sync.aligned.m16n8k16.row.col.f32.bf16.bf16.f32 "
        "{%0,%1,%2,%3}, {%4,%5,%6,%7}, {%8,%9}, {%0,%1,%2,%3};\n"
        : "+f"(d[0]), "+f"(d[1]), "+f"(d[2]), "+f"(d[3])
        : "r"(a[0]), "r"(a[1]), "r"(a[2]), "r"(a[3]), "r"(b[0]), "r"(b[1]));
}
// packed fp32x2 FMA (verified: assembles on this toolchain)
__device__ __forceinline__ float2 ffma2(float2 a, float2 b, float2 c) {
    float2 d;
    asm("{\n\t.reg .b64 ra, rb, rc, rd;\n\t"
        "mov.b64 ra, {%2, %3};\n\tmov.b64 rb, {%4, %5};\n\tmov.b64 rc, {%6, %7};\n\t"
        "fma.rn.f32x2 rd, ra, rb, rc;\n\t"
        "mov.b64 {%0, %1}, rd;\n\t}"
        : "=f"(d.x), "=f"(d.y)
        : "f"(a.x), "f"(a.y), "f"(b.x), "f"(b.y), "f"(c.x), "f"(c.y));
    return d;
}

// ---------------- prepack: fp32 -> bf16 hi/lo -------------------------------
__global__ void prepack_kernel(const float* __restrict__ s,
                               __nv_bfloat16* __restrict__ h,
                               __nv_bfloat16* __restrict__ l, int n) {
    int i = blockIdx.x * blockDim.x + threadIdx.x;
    if (i < n) {
        float x = s[i];
        __nv_bfloat16 hb = __float2bfloat16(x);
        float hf = __bfloat162float(hb);
        h[i] = hb;
        l[i] = __float2bfloat16(x - hf);
    }
}

// ---------------- HMMA bf16x3 GEMM: C[M,N] = A @ B^T ------------------------
// A: [M,4096] hi/lo bf16 row-major.  B: [N,4096] hi/lo bf16 row-major.
// CTA tile 128x128, BK=32, 8 warps (2x4), warp tile 64x32, double-buffered.
// smem rows padded to 80B -> ldmatrix conflict-free (r*80 mod 128 distinct).
#define BKC 32
#define ROWB 80
#define MAT_BYTES (128 * ROWB)         // 10240
#define STAGE_BYTES (4 * MAT_BYTES)    // 40960
#define GNC (GK / BKC)                 // 128

__global__ __launch_bounds__(256, 1)
void gemm_bf16x3(const __nv_bfloat16* __restrict__ Ah,
                 const __nv_bfloat16* __restrict__ Al,
                 const __nv_bfloat16* __restrict__ Bh,
                 const __nv_bfloat16* __restrict__ Bl,
                 float* __restrict__ C, int N) {
    extern __shared__ char sm[];
    const uint32_t sbase = smem_u32(sm);
    const int tid  = threadIdx.x;
    const int lane = tid & 31;
    const int wid  = tid >> 5;
    const int wm   = wid >> 2;   // 0..1
    const int wn   = wid & 3;    // 0..3
    const int bm   = blockIdx.y * 128;
    const int bn   = blockIdx.x * 128;

    const __nv_bfloat16* mats[4] = {Ah, Al, Bh, Bl};

    float d[4][4][4];
#pragma unroll
    for (int i = 0; i < 4; i++)
#pragma unroll
        for (int j = 0; j < 4; j++)
#pragma unroll
            for (int r = 0; r < 4; r++) d[i][j][r] = 0.f;

    // per-thread load assignment: 8 chunks of 16B per stage
    auto load_chunk = [&](int buf, int c) {
        const int kofs = c * BKC;
        const uint32_t base = sbase + buf * STAGE_BYTES;
#pragma unroll
        for (int t = 0; t < 8; t++) {
            int i   = tid + t * 256;
            int mat = i >> 9;          // 0:Ah 1:Al 2:Bh 3:Bl
            int idx = i & 511;
            int row = idx >> 2;
            int ch  = idx & 3;
            int grow = ((mat < 2) ? bm : bn) + row;
            const __nv_bfloat16* src =
                mats[mat] + (size_t)grow * GK + kofs + ch * 8;
            cpa16(base + mat * MAT_BYTES + row * ROWB + ch * 16, src);
        }
    };

    load_chunk(0, 0);
    cp_commit();

    // fragment smem addresses (relative to stage base)
    const uint32_t a_off =
        (uint32_t)((wm * 64 + (lane & 15)) * ROWB + (lane >> 4) * 16);
    const uint32_t b_off = (uint32_t)(2 * MAT_BYTES +
        (wn * 32 + (lane & 7) + ((lane >> 4) & 1) * 8) * ROWB +
        ((lane >> 3) & 1) * 16);

    for (int c = 0; c < GNC; ++c) {
        const int b = c & 1;
        if (c + 1 < GNC) {
            load_chunk(b ^ 1, c + 1);
            cp_commit();
            cp_wait1();
        } else {
            cp_wait0();
        }
        __syncthreads();

        const uint32_t stg = sbase + b * STAGE_BYTES;
#pragma unroll
        for (int ks = 0; ks < 2; ks++) {
            uint32_t ah[4][4], al[4][4], bh[2][4], bl[2][4];
#pragma unroll
            for (int i = 0; i < 4; i++)
                ldsm4(ah[i], stg + a_off + i * (16 * ROWB) + ks * 32);
#pragma unroll
            for (int i = 0; i < 4; i++)
                ldsm4(al[i], stg + MAT_BYTES + a_off + i * (16 * ROWB) + ks * 32);
#pragma unroll
            for (int jj = 0; jj < 2; jj++)
                ldsm4(bh[jj], stg + b_off + jj * (16 * ROWB) + ks * 32);
#pragma unroll
            for (int jj = 0; jj < 2; jj++)
                ldsm4(bl[jj], stg + MAT_BYTES + b_off + jj * (16 * ROWB) + ks * 32);

#pragma unroll
            for (int i = 0; i < 4; i++)
#pragma unroll
                for (int j = 0; j < 4; j++) {
                    const uint32_t* ph = &bh[j >> 1][(j & 1) * 2];
                    const uint32_t* pl = &bl[j >> 1][(j & 1) * 2];
                    mma16816(d[i][j], ah[i], ph);
                    mma16816(d[i][j], ah[i], pl);
                    mma16816(d[i][j], al[i], ph);
                }
        }
        __syncthreads();
    }

    // epilogue
    const int r0 = bm + wm * 64 + (lane >> 2);
    const int c0 = bn + wn * 32 + (lane & 3) * 2;
#pragma unroll
    for (int i = 0; i < 4; i++)
#pragma unroll
        for (int j = 0; j < 4; j++) {
            int row = r0 + i * 16;
            int col = c0 + j * 8;
            *(float2*)&C[(size_t)row * N + col] =
                make_float2(d[i][j][0], d[i][j][1]);
            *(float2*)&C[(size_t)(row + 8) * N + col] =
                make_float2(d[i][j][2], d[i][j][3]);
        }
}

// ---------------- RoPE ------------------------------------------------------
__global__ void rope_kernel(const float* __restrict__ fc, const float* __restrict__ fs) {
    const int NQ = BB * TT * NH * (HD / 2);
    const int NK = BB * TT * NKV * (HD / 2);
    int i = blockIdx.x * blockDim.x + threadIdx.x;
    if (i < NQ) {
        int di = i & 63;
        int h  = (i >> 6) & 31;
        int t  = (i >> 11) & 2047;
        int b  = i >> 22;
        size_t base = (((size_t)(b * TT + t) * NH + h) << 7) + 2 * di;
        float c = fc[t * 64 + di], s = fs[t * 64 + di];
        float xr = g_q[base], xi = g_q[base + 1];
        g_q[base]     = xr * c - xi * s;
        g_q[base + 1] = xr * s + xi * c;
    } else if (i < NQ + NK) {
        int j = i - NQ;
        int di = j & 63;
        int h  = (j >> 6) & 7;
        int t  = (j >> 9) & 2047;
        int b  = j >> 20;
        size_t base = (((size_t)(b * TT + t) * NKV + h) << 7) + 2 * di;
        float c = fc[t * 64 + di], s = fs[t * 64 + di];
        float xr = g_k[base], xi = g_k[base + 1];
        g_k[base]     = xr * c - xi * s;
        g_k[base + 1] = xr * s + xi * c;
    }
}

// ---------------- flash attention (fp32, FFMA2 inner loops) -----------------
#define QSTR 132
#define PSTR 68
__global__ __launch_bounds__(256) void flash_kernel() {
    extern __shared__ float smem[];
    float* sq = smem;
    float* sk = sq + 64 * QSTR;
    float* sv = sk + 64 * QSTR;
    float* sp = sv + 64 * QSTR;

    const int tid = threadIdx.x;
    const int ry = tid >> 4;
    const int cx = tid & 15;
    const int q0 = blockIdx.x * 64;
    const int h  = blockIdx.y;
    const int b  = blockIdx.z;
    const int kh = h & 7;

    {
        const size_t qbase = ((size_t)(b * TT + q0) * NH + h) << 7;
        for (int i = tid; i < 64 * 32; i += 256) {
            int row = i >> 5, d4 = (i & 31) << 2;
            *(float4*)(sq + row * QSTR + d4) =
                *(const float4*)(g_q + qbase + (size_t)row * (NH * HD) + d4);
        }
    }

    float2 o2[4][4];
    float m[4], l[4];
#pragma unroll
    for (int r = 0; r < 4; r++) {
        m[r] = -1e30f; l[r] = 0.f;
#pragma unroll
        for (int c = 0; c < 4; c++) o2[r][c] = make_float2(0.f, 0.f);
    }
    const float scale = 0.08838834764831845f;

    for (int s0 = 0; s0 < TT; s0 += 64) {
        __syncthreads();
        {
            const size_t kbase = ((size_t)(b * TT + s0) * NKV + kh) << 7;
            for (int i = tid; i < 64 * 32; i += 256) {
                int row = i >> 5, d4 = (i & 31) << 2;
                size_t g = kbase + (size_t)row * (NKV * HD) + d4;
                *(float4*)(sk + row * QSTR + d4) = *(const float4*)(g_k + g);
                *(float4*)(sv + row * QSTR + d4) = *(const float4*)(g_v + g);
            }
        }
        __syncthreads();

        float2 acc2[4][4];
#pragma unroll
        for (int rr = 0; rr < 4; rr++)
#pragma unroll
            for (int jj = 0; jj < 4; jj++) acc2[rr][jj] = make_float2(0.f, 0.f);

        for (int dd = 0; dd < HD; dd += 4) {
            float4 qv[4], kv[4];
#pragma unroll
            for (int rr = 0; rr < 4; rr++)
                qv[rr] = *(const float4*)(sq + (ry + 16 * rr) * QSTR + dd);
#pragma unroll
            for (int jj = 0; jj < 4; jj++)
                kv[jj] = *(const float4*)(sk + (cx + 16 * jj) * QSTR + dd);
#pragma unroll
            for (int rr = 0; rr < 4; rr++)
#pragma unroll
                for (int jj = 0; jj < 4; jj++) {
                    acc2[rr][jj] = ffma2(make_float2(qv[rr].x, qv[rr].y),
                                         make_float2(kv[jj].x, kv[jj].y), acc2[rr][jj]);
                    acc2[rr][jj] = ffma2(make_float2(qv[rr].z, qv[rr].w),
                                         make_float2(kv[jj].z, kv[jj].w), acc2[rr][jj]);
                }
        }

#pragma unroll
        for (int rr = 0; rr < 4; rr++) {
            float sc[4];
#pragma unroll
            for (int jj = 0; jj < 4; jj++)
                sc[jj] = (acc2[rr][jj].x + acc2[rr][jj].y) * scale;
            float mt = sc[0];
#pragma unroll
            for (int jj = 1; jj < 4; jj++) mt = fmaxf(mt, sc[jj]);
#pragma unroll
            for (int off = 8; off > 0; off >>= 1)
                mt = fmaxf(mt, __shfl_xor_sync(0xffffffffu, mt, off));
            float mnew = fmaxf(m[rr], mt);
            float alpha = __expf(m[rr] - mnew);
            float ls = 0.f;
#pragma unroll
            for (int jj = 0; jj < 4; jj++) {
                sc[jj] = __expf(sc[jj] - mnew);
                ls += sc[jj];
            }
#pragma unroll
            for (int off = 8; off > 0; off >>= 1)
                ls += __shfl_xor_sync(0xffffffffu, ls, off);
            l[rr] = l[rr] * alpha + ls;
            m[rr] = mnew;
#pragma unroll
            for (int jj = 0; jj < 4; jj++)
                sp[(ry + 16 * rr) * PSTR + cx + 16 * jj] = sc[jj];
#pragma unroll
            for (int c = 0; c < 4; c++) {
                o2[rr][c].x *= alpha;
                o2[rr][c].y *= alpha;
            }
        }
        __syncthreads();

        for (int s = 0; s < 64; s++) {
            float p[4];
#pragma unroll
            for (int rr = 0; rr < 4; rr++)
                p[rr] = sp[(ry + 16 * rr) * PSTR + s];
            float4 v0 = *(const float4*)(sv + s * QSTR + cx * 8);
            float4 v1 = *(const float4*)(sv + s * QSTR + cx * 8 + 4);
            float2 vp[4] = {make_float2(v0.x, v0.y), make_float2(v0.z, v0.w),
                            make_float2(v1.x, v1.y), make_float2(v1.z, v1.w)};
#pragma unroll
            for (int rr = 0; rr < 4; rr++) {
                float2 pp = make_float2(p[rr], p[rr]);
#pragma unroll
                for (int c = 0; c < 4; c++)
                    o2[rr][c] = ffma2(pp, vp[c], o2[rr][c]);
            }
        }
    }

#pragma unroll
    for (int rr = 0; rr < 4; rr++) {
        float inv = 1.0f / l[rr];
        int t = q0 + ry + 16 * rr;
        size_t base = (((size_t)(b * TT + t) * NH + h) << 7) + cx * 8;
        float4 c0 = make_float4(o2[rr][0].x * inv, o2[rr][0].y * inv,
                                o2[rr][1].x * inv, o2[rr][1].y * inv);
        float4 c1 = make_float4(o2[rr][2].x * inv, o2[rr][2].y * inv,
                                o2[rr][3].x * inv, o2[rr][3].y * inv);
        *(float4*)(g_ctx + base) = c0;
        *(float4*)(g_ctx + base + 4) = c1;
    }
}

// ---------------------------------------------------------------------------
extern "C" void kernel_launch(void* const* d_in, const int* in_sizes, int n_in,
                              void* d_out, int out_size) {
    const float* x  = (const float*)d_in[0];
    const float* wq = (const float*)d_in[1];
    const float* wk = (const float*)d_in[2];
    const float* wv = (const float*)d_in[3];
    const float* wo = (const float*)d_in[4];
    const float* fc = (const float*)d_in[5];
    const float* fs = (const float*)d_in[6];
    float* out = (float*)d_out;

    float *qp, *kp, *vp, *ctxp;
    cudaGetSymbolAddress((void**)&qp,   g_q);
    cudaGetSymbolAddress((void**)&kp,   g_k);
    cudaGetSymbolAddress((void**)&vp,   g_v);
    cudaGetSymbolAddress((void**)&ctxp, g_ctx);
    __nv_bfloat16 *xh, *xl, *wqh, *wql, *wkh, *wkl, *wvh, *wvl, *woh, *wol, *ch, *cl;
    cudaGetSymbolAddress((void**)&xh,  g_xh);  cudaGetSymbolAddress((void**)&xl,  g_xl);
    cudaGetSymbolAddress((void**)&wqh, g_wqh); cudaGetSymbolAddress((void**)&wql, g_wql);
    cudaGetSymbolAddress((void**)&wkh, g_wkh); cudaGetSymbolAddress((void**)&wkl, g_wkl);
    cudaGetSymbolAddress((void**)&wvh, g_wvh); cudaGetSymbolAddress((void**)&wvl, g_wvl);
    cudaGetSymbolAddress((void**)&woh, g_woh); cudaGetSymbolAddress((void**)&wol, g_wol);
    cudaGetSymbolAddress((void**)&ch,  g_ch);  cudaGetSymbolAddress((void**)&cl,  g_cl);

    const int NBIG = MTOK * DIM;       // 16.7M
    const int NKW  = NKV * HD * DIM;   // 4.2M

    // hi/lo prepack
    prepack_kernel<<<(NBIG + 255) / 256, 256>>>(x,  xh,  xl,  NBIG);
    prepack_kernel<<<(NBIG + 255) / 256, 256>>>(wq, wqh, wql, NBIG);
    prepack_kernel<<<(NKW  + 255) / 256, 256>>>(wk, wkh, wkl, NKW);
    prepack_kernel<<<(NKW  + 255) / 256, 256>>>(wv, wvh, wvl, NKW);
    prepack_kernel<<<(NBIG + 255) / 256, 256>>>(wo, woh, wol, NBIG);

    const int GEMM_SMEM = 2 * STAGE_BYTES;  // 81920
    cudaFuncSetAttribute(gemm_bf16x3,
                         cudaFuncAttributeMaxDynamicSharedMemorySize, GEMM_SMEM);

    // projections: q, k, v
    gemm_bf16x3<<<dim3(DIM / 128, MTOK / 128), 256, GEMM_SMEM>>>(xh, xl, wqh, wql, qp, DIM);
    gemm_bf16x3<<<dim3((NKV * HD) / 128, MTOK / 128), 256, GEMM_SMEM>>>(xh, xl, wkh, wkl, kp, NKV * HD);
    gemm_bf16x3<<<dim3((NKV * HD) / 128, MTOK / 128), 256, GEMM_SMEM>>>(xh, xl, wvh, wvl, vp, NKV * HD);

    // RoPE
    {
        int total = BB * TT * (NH + NKV) * (HD / 2);
        rope_kernel<<<(total + 255) / 256, 256>>>(fc, fs);
    }

    // flash attention
    {
        size_t shmem = (3 * 64 * QSTR + 64 * PSTR) * sizeof(float);
        cudaFuncSetAttribute(flash_kernel,
                             cudaFuncAttributeMaxDynamicSharedMemorySize, (int)shmem);
        flash_kernel<<<dim3(TT / 64, NH, BB), 256, shmem>>>();
    }

    // output projection
    prepack_kernel<<<(NBIG + 255) / 256, 256>>>(ctxp, ch, cl, NBIG);
    gemm_bf16x3<<<dim3(DIM / 128, MTOK / 128), 256, GEMM_SMEM>>>(ch, cl, woh, wol, out, DIM);
}

// round 5
// speedup vs baseline: 3.4266x; 1.9194x over previous
#include <cuda_runtime.h>
#include <cuda_bf16.h>
#include <cuda_fp16.h>
#include <math.h>
#include <stdint.h>

#define BB 2
#define TT 2048
#define DIM 4096
#define NH 32
#define NKV 8
#define HD 128
#define MTOK (BB * TT)
#define GK 4096

// ---------------- device scratch ---------------------------------------
__device__ __align__(16) float g_q[(size_t)MTOK * NH * HD];
__device__ __align__(16) float g_k[(size_t)MTOK * NKV * HD];
__device__ __align__(16) float g_v[(size_t)MTOK * NKV * HD];

__device__ __align__(16) __nv_bfloat16 g_xh[(size_t)MTOK * DIM];
__device__ __align__(16) __nv_bfloat16 g_xl[(size_t)MTOK * DIM];
__device__ __align__(16) __nv_bfloat16 g_wqh[(size_t)DIM * DIM];
__device__ __align__(16) __nv_bfloat16 g_wql[(size_t)DIM * DIM];
__device__ __align__(16) __nv_bfloat16 g_wkh[(size_t)NKV * HD * DIM];
__device__ __align__(16) __nv_bfloat16 g_wkl[(size_t)NKV * HD * DIM];
__device__ __align__(16) __nv_bfloat16 g_wvh[(size_t)NKV * HD * DIM];
__device__ __align__(16) __nv_bfloat16 g_wvl[(size_t)NKV * HD * DIM];
__device__ __align__(16) __nv_bfloat16 g_woh[(size_t)DIM * DIM];
__device__ __align__(16) __nv_bfloat16 g_wol[(size_t)DIM * DIM];
__device__ __align__(16) __nv_bfloat16 g_ch[(size_t)MTOK * DIM];
__device__ __align__(16) __nv_bfloat16 g_cl[(size_t)MTOK * DIM];

// head-major fp16 q/k/v for flash
__device__ __align__(16) __half g_fqh[(size_t)BB * NH * TT * HD];
__device__ __align__(16) __half g_fql[(size_t)BB * NH * TT * HD];
__device__ __align__(16) __half g_fkh[(size_t)BB * NKV * TT * HD];
__device__ __align__(16) __half g_fkl[(size_t)BB * NKV * TT * HD];
__device__ __align__(16) __half g_fv [(size_t)BB * NKV * TT * HD];

// ---------------- helpers ----------------------------------------------
__device__ __forceinline__ uint32_t smem_u32(const void* p) {
    uint32_t a;
    asm("{ .reg .u64 t; cvta.to.shared.u64 t, %1; cvt.u32.u64 %0, t; }"
        : "=r"(a) : "l"(p));
    return a;
}
__device__ __forceinline__ void cpa16(uint32_t dst, const void* src) {
    asm volatile("cp.async.cg.shared.global [%0], [%1], 16;"
                 :: "r"(dst), "l"(src) : "memory");
}
__device__ __forceinline__ void cp_commit() {
    asm volatile("cp.async.commit_group;" ::: "memory");
}
__device__ __forceinline__ void cp_wait1() {
    asm volatile("cp.async.wait_group 1;" ::: "memory");
}
__device__ __forceinline__ void cp_wait0() {
    asm volatile("cp.async.wait_group 0;" ::: "memory");
}
__device__ __forceinline__ void ldsm4(uint32_t* r, uint32_t addr) {
    asm volatile("ldmatrix.sync.aligned.m8n8.x4.shared.b16 {%0,%1,%2,%3}, [%4];"
                 : "=r"(r[0]), "=r"(r[1]), "=r"(r[2]), "=r"(r[3]) : "r"(addr));
}
__device__ __forceinline__ void ldsm4t(uint32_t* r, uint32_t addr) {
    asm volatile("ldmatrix.sync.aligned.m8n8.x4.trans.shared.b16 {%0,%1,%2,%3}, [%4];"
                 : "=r"(r[0]), "=r"(r[1]), "=r"(r[2]), "=r"(r[3]) : "r"(addr));
}
__device__ __forceinline__ void mma_bf16(float* d, const uint32_t* a, const uint32_t* b) {
    asm volatile(
        "mma.sync.aligned.m16n8k16.row.col.f32.bf16.bf16.f32 "
        "{%0,%1,%2,%3}, {%4,%5,%6,%7}, {%8,%9}, {%0,%1,%2,%3};\n"
        : "+f"(d[0]), "+f"(d[1]), "+f"(d[2]), "+f"(d[3])
        : "r"(a[0]), "r"(a[1]), "r"(a[2]), "r"(a[3]), "r"(b[0]), "r"(b[1]));
}
__device__ __forceinline__ void mma_f16(float* d, const uint32_t* a, const uint32_t* b) {
    asm volatile(
        "mma.sync.aligned.m16n8k16.row.col.f32.f16.f16.f32 "
        "{%0,%1,%2,%3}, {%4,%5,%6,%7}, {%8,%9}, {%0,%1,%2,%3};\n"
        : "+f"(d[0]), "+f"(d[1]), "+f"(d[2]), "+f"(d[3])
        : "r"(a[0]), "r"(a[1]), "r"(a[2]), "r"(a[3]), "r"(b[0]), "r"(b[1]));
}
__device__ __forceinline__ uint32_t pack_h2(float lo, float hi) {
    __half2 h = __floats2half2_rn(lo, hi);
    return *(uint32_t*)&h;
}

// ---------------- prepack: fp32 -> bf16 hi/lo ---------------------------
__global__ void prepack_kernel(const float* __restrict__ s,
                               __nv_bfloat16* __restrict__ h,
                               __nv_bfloat16* __restrict__ l, int n) {
    int i = blockIdx.x * blockDim.x + threadIdx.x;
    if (i < n) {
        float x = s[i];
        __nv_bfloat16 hb = __float2bfloat16(x);
        h[i] = hb;
        l[i] = __float2bfloat16(x - __bfloat162float(hb));
    }
}

// ---------------- HMMA bf16x3 GEMM: C[M,N] = A @ B^T --------------------
#define BKC 32
#define ROWB 80
#define MAT_BYTES (128 * ROWB)
#define STAGE_BYTES (4 * MAT_BYTES)    // 40960
#define GNC (GK / BKC)                 // 128

__global__ __launch_bounds__(256, 1)
void gemm_bf16x3(const __nv_bfloat16* __restrict__ Ah,
                 const __nv_bfloat16* __restrict__ Al,
                 const __nv_bfloat16* __restrict__ Bh,
                 const __nv_bfloat16* __restrict__ Bl,
                 float* __restrict__ C, int N) {
    extern __shared__ char sm[];
    const uint32_t sbase = smem_u32(sm);
    const int tid  = threadIdx.x;
    const int lane = tid & 31;
    const int wid  = tid >> 5;
    const int wm   = wid >> 2;
    const int wn   = wid & 3;
    const int bm   = blockIdx.y * 128;
    const int bn   = blockIdx.x * 128;

    const __nv_bfloat16* mats[4] = {Ah, Al, Bh, Bl};

    float d[4][4][4];
#pragma unroll
    for (int i = 0; i < 4; i++)
#pragma unroll
        for (int j = 0; j < 4; j++)
#pragma unroll
            for (int r = 0; r < 4; r++) d[i][j][r] = 0.f;

    auto load_chunk = [&](int buf, int c) {
        const int kofs = c * BKC;
        const uint32_t base = sbase + buf * STAGE_BYTES;
#pragma unroll
        for (int t = 0; t < 8; t++) {
            int i   = tid + t * 256;
            int mat = i >> 9;
            int idx = i & 511;
            int row = idx >> 2;
            int ch  = idx & 3;
            int grow = ((mat < 2) ? bm : bn) + row;
            cpa16(base + mat * MAT_BYTES + row * ROWB + ch * 16,
                  mats[mat] + (size_t)grow * GK + kofs + ch * 8);
        }
    };

    load_chunk(0, 0); cp_commit();
    load_chunk(1, 1); cp_commit();

    const uint32_t a_off =
        (uint32_t)((wm * 64 + (lane & 15)) * ROWB + (lane >> 4) * 16);
    const uint32_t b_off = (uint32_t)(2 * MAT_BYTES +
        (wn * 32 + (lane & 7) + ((lane >> 4) & 1) * 8) * ROWB +
        ((lane >> 3) & 1) * 16);

    for (int c = 0; c < GNC; ++c) {
        if (c + 1 < GNC) cp_wait1(); else cp_wait0();
        __syncthreads();
        if (c + 2 < GNC) { load_chunk((c + 2) % 3, c + 2); cp_commit(); }

        const uint32_t stg = sbase + (c % 3) * STAGE_BYTES;
#pragma unroll
        for (int ks = 0; ks < 2; ks++) {
            uint32_t ah[4][4], al[4][4], bh[2][4], bl[2][4];
#pragma unroll
            for (int i = 0; i < 4; i++)
                ldsm4(ah[i], stg + a_off + i * (16 * ROWB) + ks * 32);
#pragma unroll
            for (int i = 0; i < 4; i++)
                ldsm4(al[i], stg + MAT_BYTES + a_off + i * (16 * ROWB) + ks * 32);
#pragma unroll
            for (int jj = 0; jj < 2; jj++)
                ldsm4(bh[jj], stg + b_off + jj * (16 * ROWB) + ks * 32);
#pragma unroll
            for (int jj = 0; jj < 2; jj++)
                ldsm4(bl[jj], stg + MAT_BYTES + b_off + jj * (16 * ROWB) + ks * 32);

#pragma unroll
            for (int i = 0; i < 4; i++)
#pragma unroll
                for (int j = 0; j < 4; j++) {
                    const uint32_t* ph = &bh[j >> 1][(j & 1) * 2];
                    const uint32_t* pl = &bl[j >> 1][(j & 1) * 2];
                    mma_bf16(d[i][j], ah[i], ph);
                    mma_bf16(d[i][j], ah[i], pl);
                    mma_bf16(d[i][j], al[i], ph);
                }
        }
    }

    const int r0 = bm + wm * 64 + (lane >> 2);
    const int c0 = bn + wn * 32 + (lane & 3) * 2;
#pragma unroll
    for (int i = 0; i < 4; i++)
#pragma unroll
        for (int j = 0; j < 4; j++) {
            int row = r0 + i * 16;
            int col = c0 + j * 8;
            *(float2*)&C[(size_t)row * N + col] =
                make_float2(d[i][j][0], d[i][j][1]);
            *(float2*)&C[(size_t)(row + 8) * N + col] =
                make_float2(d[i][j][2], d[i][j][3]);
        }
}

// ---------------- rope + fp16 pack (head-major) -------------------------
#define NQP (BB * NH * TT * (HD / 2))    // 8388608
#define NKP (BB * NKV * TT * (HD / 2))   // 2097152
#define NVE (BB * NKV * TT * HD)         // 4194304
__global__ void rope_pack(const float* __restrict__ fc, const float* __restrict__ fs) {
    int i = blockIdx.x * blockDim.x + threadIdx.x;
    if (i < NQP) {
        int dp = i & 63, t = (i >> 6) & 2047, hh = (i >> 17) & 31, b = i >> 22;
        size_t src = (((size_t)(b * TT + t) * NH + hh) << 7) + 2 * dp;
        float c = fc[t * 64 + dp], s = fs[t * 64 + dp];
        float xr = g_q[src], xi = g_q[src + 1];
        float o0 = xr * c - xi * s;
        float o1 = xr * s + xi * c;
        size_t dst = (((size_t)(b * NH + hh) * TT + t) << 7) + 2 * dp;
        __half h0 = __float2half_rn(o0), h1 = __float2half_rn(o1);
        g_fqh[dst] = h0;     g_fqh[dst + 1] = h1;
        g_fql[dst]     = __float2half_rn(o0 - __half2float(h0));
        g_fql[dst + 1] = __float2half_rn(o1 - __half2float(h1));
    } else if (i < NQP + NKP) {
        int j = i - NQP;
        int dp = j & 63, t = (j >> 6) & 2047, hh = (j >> 17) & 7, b = j >> 20;
        size_t src = (((size_t)(b * TT + t) * NKV + hh) << 7) + 2 * dp;
        float c = fc[t * 64 + dp], s = fs[t * 64 + dp];
        float xr = g_k[src], xi = g_k[src + 1];
        float o0 = xr * c - xi * s;
        float o1 = xr * s + xi * c;
        size_t dst = (((size_t)(b * NKV + hh) * TT + t) << 7) + 2 * dp;
        __half h0 = __float2half_rn(o0), h1 = __float2half_rn(o1);
        g_fkh[dst] = h0;     g_fkh[dst + 1] = h1;
        g_fkl[dst]     = __float2half_rn(o0 - __half2float(h0));
        g_fkl[dst + 1] = __float2half_rn(o1 - __half2float(h1));
    } else if (i < NQP + NKP + NVE) {
        int e = i - NQP - NKP;
        int dd = e & 127, t = (e >> 7) & 2047, hh = (e >> 18) & 7, b = e >> 21;
        size_t src = (((size_t)(b * TT + t) * NKV + hh) << 7) + dd;
        size_t dst = (((size_t)(b * NKV + hh) * TT + t) << 7) + dd;
        g_fv[dst] = __float2half_rn(g_v[src]);
    }
}

// ---------------- flash attention: fp16 HMMA, FA2 register softmax -----
#define FSTG 65536
#define FSTGB 49152
#define FSMEM (FSTG + 2 * FSTGB)        // 163840
#define NSTILE (TT / 64)                // 32

__global__ __launch_bounds__(256, 1)
void flash_hmma(const __half* __restrict__ Qh, const __half* __restrict__ Ql,
                const __half* __restrict__ Kh, const __half* __restrict__ Kl,
                const __half* __restrict__ Vv,
                __nv_bfloat16* __restrict__ Ch, __nv_bfloat16* __restrict__ Cl) {
    extern __shared__ char sm[];
    const uint32_t sb = smem_u32(sm);
    const int tid = threadIdx.x, lane = tid & 31, w = tid >> 5;
    const int t0 = blockIdx.x * 128;
    const int h  = blockIdx.y;
    const int b  = blockIdx.z;
    const int kh = h & 7;

    const __half* qhp = Qh + (((size_t)(b * NH + h) * TT + t0) << 7);
    const __half* qlp = Ql + (((size_t)(b * NH + h) * TT + t0) << 7);
    const __half* khp = Kh + (((size_t)(b * NKV + kh) * TT) << 7);
    const __half* klp = Kl + (((size_t)(b * NKV + kh) * TT) << 7);
    const __half* vhp = Vv + (((size_t)(b * NKV + kh) * TT) << 7);

    // Q tile hi/lo: 128 rows x 16 chunks x 2 arrays = 4096 16B chunks
#pragma unroll
    for (int it = 0; it < 16; it++) {
        int i = tid + it * 256;
        int arr = i >> 11, ci = i & 2047;
        int r = ci >> 4, c = ci & 15;
        cpa16(sb + arr * 32768 + r * 256 + ((c ^ (r & 7)) * 16),
              (arr ? qlp : qhp) + r * HD + c * 8);
    }
    cp_commit();

    auto load_kv = [&](int stg, int s) {
        const uint32_t bs = sb + FSTG + stg * FSTGB;
        const __half* srcs[3] = {khp + (size_t)s * 64 * HD,
                                 klp + (size_t)s * 64 * HD,
                                 vhp + (size_t)s * 64 * HD};
#pragma unroll
        for (int it = 0; it < 12; it++) {
            int i = tid + it * 256;
            int arr = i >> 10, ci = i & 1023;
            int r = ci >> 4, c = ci & 15;
            cpa16(bs + arr * 16384 + r * 256 + ((c ^ (r & 7)) * 16),
                  srcs[arr] + r * HD + c * 8);
        }
    };
    load_kv(0, 0); cp_commit();
    load_kv(1, 1); cp_commit();

    float oa[16][4];
#pragma unroll
    for (int nt = 0; nt < 16; nt++)
#pragma unroll
        for (int c = 0; c < 4; c++) oa[nt][c] = 0.f;
    float m0 = -1e30f, m1 = -1e30f, l0 = 0.f, l1 = 0.f;
    const float scale = 0.08838834764831845f;

    const int qr = w * 16 + (lane & 15);
    const uint32_t qrow = sb + qr * 256;
    const int kr = (lane & 7) + ((lane >> 4) & 1) * 8;
    const int vr = lane & 15;

    for (int s = 0; s < NSTILE; s++) {
        if (s + 1 < NSTILE) cp_wait1(); else cp_wait0();
        __syncthreads();
        const uint32_t kb = sb + FSTG + (s & 1) * FSTGB;

        // ---- S = Q K^T (fp16 3-pass) ----
        float sa[8][4];
#pragma unroll
        for (int j = 0; j < 8; j++)
#pragma unroll
            for (int c = 0; c < 4; c++) sa[j][c] = 0.f;

#pragma unroll
        for (int kc = 0; kc < 8; kc++) {
            uint32_t qa[4], qb[4];
            {
                int c = 2 * kc + (lane >> 4);
                uint32_t a = qrow + ((c ^ (qr & 7)) * 16);
                ldsm4(qa, a);
                ldsm4(qb, a + 32768);
            }
#pragma unroll
            for (int kt = 0; kt < 4; kt++) {
                uint32_t kfh[4], kfl[4];
                int krr = kt * 16 + kr;
                int kcc = 2 * kc + ((lane >> 3) & 1);
                uint32_t ka = kb + krr * 256 + ((kcc ^ (krr & 7)) * 16);
                ldsm4(kfh, ka);
                ldsm4(kfl, ka + 16384);
#pragma unroll
                for (int hn = 0; hn < 2; hn++) {
                    int j = kt * 2 + hn;
                    mma_f16(sa[j], qa, &kfh[hn * 2]);
                    mma_f16(sa[j], qa, &kfl[hn * 2]);
                    mma_f16(sa[j], qb, &kfh[hn * 2]);
                }
            }
        }

        // ---- online softmax (registers) ----
        float mx0 = -1e30f, mx1 = -1e30f;
#pragma unroll
        for (int j = 0; j < 8; j++) {
#pragma unroll
            for (int c = 0; c < 4; c++) sa[j][c] *= scale;
            mx0 = fmaxf(mx0, fmaxf(sa[j][0], sa[j][1]));
            mx1 = fmaxf(mx1, fmaxf(sa[j][2], sa[j][3]));
        }
#pragma unroll
        for (int off = 1; off <= 2; off <<= 1) {
            mx0 = fmaxf(mx0, __shfl_xor_sync(0xffffffffu, mx0, off));
            mx1 = fmaxf(mx1, __shfl_xor_sync(0xffffffffu, mx1, off));
        }
        float nm0 = fmaxf(m0, mx0), nm1 = fmaxf(m1, mx1);
        float al0 = __expf(m0 - nm0), al1 = __expf(m1 - nm1);
        float rs0 = 0.f, rs1 = 0.f;
#pragma unroll
        for (int j = 0; j < 8; j++) {
            sa[j][0] = __expf(sa[j][0] - nm0);
            sa[j][1] = __expf(sa[j][1] - nm0);
            sa[j][2] = __expf(sa[j][2] - nm1);
            sa[j][3] = __expf(sa[j][3] - nm1);
            rs0 += sa[j][0] + sa[j][1];
            rs1 += sa[j][2] + sa[j][3];
        }
#pragma unroll
        for (int off = 1; off <= 2; off <<= 1) {
            rs0 += __shfl_xor_sync(0xffffffffu, rs0, off);
            rs1 += __shfl_xor_sync(0xffffffffu, rs1, off);
        }
        l0 = l0 * al0 + rs0;  l1 = l1 * al1 + rs1;
        m0 = nm0;  m1 = nm1;
#pragma unroll
        for (int nt = 0; nt < 16; nt++) {
            oa[nt][0] *= al0; oa[nt][1] *= al0;
            oa[nt][2] *= al1; oa[nt][3] *= al1;
        }

        // ---- O += P V ----
#pragma unroll
        for (int kc2 = 0; kc2 < 4; kc2++) {
            uint32_t pa[4];
            pa[0] = pack_h2(sa[2 * kc2][0],     sa[2 * kc2][1]);
            pa[1] = pack_h2(sa[2 * kc2][2],     sa[2 * kc2][3]);
            pa[2] = pack_h2(sa[2 * kc2 + 1][0], sa[2 * kc2 + 1][1]);
            pa[3] = pack_h2(sa[2 * kc2 + 1][2], sa[2 * kc2 + 1][3]);
            int vrr = kc2 * 16 + vr;
            uint32_t vrow = kb + 32768 + vrr * 256;
#pragma unroll
            for (int nt2 = 0; nt2 < 8; nt2++) {
                uint32_t vf[4];
                int vc = nt2 * 2 + (lane >> 4);
                ldsm4t(vf, vrow + ((vc ^ (vrr & 7)) * 16));
                mma_f16(oa[nt2 * 2],     pa, &vf[0]);
                mma_f16(oa[nt2 * 2 + 1], pa, &vf[2]);
            }
        }

        __syncthreads();
        if (s + 2 < NSTILE) { load_kv(s & 1, s + 2); cp_commit(); }
    }

    // ---- epilogue: normalize, split bf16 hi/lo, store ctx --------------
    float i0 = 1.f / l0, i1 = 1.f / l1;
    int rg0 = t0 + w * 16 + (lane >> 2);
    size_t row0 = (size_t)(b * TT + rg0) * DIM;
    size_t row1 = row0 + 8 * DIM;
#pragma unroll
    for (int nt = 0; nt < 16; nt++) {
        int col = h * HD + nt * 8 + (lane & 3) * 2;
        {
            float f0 = oa[nt][0] * i0, f1 = oa[nt][1] * i0;
            __nv_bfloat16 h0 = __float2bfloat16(f0), h1 = __float2bfloat16(f1);
            __nv_bfloat162 hv; hv.x = h0; hv.y = h1;
            *(uint32_t*)(Ch + row0 + col) = *(uint32_t*)&hv;
            __nv_bfloat162 lv;
            lv.x = __float2bfloat16(f0 - __bfloat162float(h0));
            lv.y = __float2bfloat16(f1 - __bfloat162float(h1));
            *(uint32_t*)(Cl + row0 + col) = *(uint32_t*)&lv;
        }
        {
            float f0 = oa[nt][2] * i1, f1 = oa[nt][3] * i1;
            __nv_bfloat16 h0 = __float2bfloat16(f0), h1 = __float2bfloat16(f1);
            __nv_bfloat162 hv; hv.x = h0; hv.y = h1;
            *(uint32_t*)(Ch + row1 + col) = *(uint32_t*)&hv;
            __nv_bfloat162 lv;
            lv.x = __float2bfloat16(f0 - __bfloat162float(h0));
            lv.y = __float2bfloat16(f1 - __bfloat162float(h1));
            *(uint32_t*)(Cl + row1 + col) = *(uint32_t*)&lv;
        }
    }
}

// ---------------------------------------------------------------------------
extern "C" void kernel_launch(void* const* d_in, const int* in_sizes, int n_in,
                              void* d_out, int out_size) {
    const float* x  = (const float*)d_in[0];
    const float* wq = (const float*)d_in[1];
    const float* wk = (const float*)d_in[2];
    const float* wv = (const float*)d_in[3];
    const float* wo = (const float*)d_in[4];
    const float* fc = (const float*)d_in[5];
    const float* fs = (const float*)d_in[6];
    float* out = (float*)d_out;

    float *qp, *kp, *vp;
    cudaGetSymbolAddress((void**)&qp, g_q);
    cudaGetSymbolAddress((void**)&kp, g_k);
    cudaGetSymbolAddress((void**)&vp, g_v);
    __nv_bfloat16 *xh, *xl, *wqh, *wql, *wkh, *wkl, *wvh, *wvl, *woh, *wol, *ch, *cl;
    cudaGetSymbolAddress((void**)&xh,  g_xh);  cudaGetSymbolAddress((void**)&xl,  g_xl);
    cudaGetSymbolAddress((void**)&wqh, g_wqh); cudaGetSymbolAddress((void**)&wql, g_wql);
    cudaGetSymbolAddress((void**)&wkh, g_wkh); cudaGetSymbolAddress((void**)&wkl, g_wkl);
    cudaGetSymbolAddress((void**)&wvh, g_wvh); cudaGetSymbolAddress((void**)&wvl, g_wvl);
    cudaGetSymbolAddress((void**)&woh, g_woh); cudaGetSymbolAddress((void**)&wol, g_wol);
    cudaGetSymbolAddress((void**)&ch,  g_ch);  cudaGetSymbolAddress((void**)&cl,  g_cl);
    __half *fqh, *fql, *fkh, *fkl, *fv;
    cudaGetSymbolAddress((void**)&fqh, g_fqh); cudaGetSymbolAddress((void**)&fql, g_fql);
    cudaGetSymbolAddress((void**)&fkh, g_fkh); cudaGetSymbolAddress((void**)&fkl, g_fkl);
    cudaGetSymbolAddress((void**)&fv,  g_fv);

    const int NBIG = MTOK * DIM;
    const int NKW  = NKV * HD * DIM;

    prepack_kernel<<<(NBIG + 255) / 256, 256>>>(x,  xh,  xl,  NBIG);
    prepack_kernel<<<(NBIG + 255) / 256, 256>>>(wq, wqh, wql, NBIG);
    prepack_kernel<<<(NKW  + 255) / 256, 256>>>(wk, wkh, wkl, NKW);
    prepack_kernel<<<(NKW  + 255) / 256, 256>>>(wv, wvh, wvl, NKW);
    prepack_kernel<<<(NBIG + 255) / 256, 256>>>(wo, woh, wol, NBIG);

    const int GEMM_SMEM = 3 * STAGE_BYTES;   // 122880
    cudaFuncSetAttribute(gemm_bf16x3,
                         cudaFuncAttributeMaxDynamicSharedMemorySize, GEMM_SMEM);

    gemm_bf16x3<<<dim3(DIM / 128, MTOK / 128), 256, GEMM_SMEM>>>(xh, xl, wqh, wql, qp, DIM);
    gemm_bf16x3<<<dim3((NKV * HD) / 128, MTOK / 128), 256, GEMM_SMEM>>>(xh, xl, wkh, wkl, kp, NKV * HD);
    gemm_bf16x3<<<dim3((NKV * HD) / 128, MTOK / 128), 256, GEMM_SMEM>>>(xh, xl, wvh, wvl, vp, NKV * HD);

    {
        int total = NQP + NKP + NVE;
        rope_pack<<<(total + 255) / 256, 256>>>(fc, fs);
    }

    cudaFuncSetAttribute(flash_hmma,
                         cudaFuncAttributeMaxDynamicSharedMemorySize, FSMEM);
    flash_hmma<<<dim3(TT / 128, NH, BB), 256, FSMEM>>>(fqh, fql, fkh, fkl, fv, ch, cl);

    gemm_bf16x3<<<dim3(DIM / 128, MTOK / 128), 256, GEMM_SMEM>>>(ch, cl, woh, wol, out, DIM);
}

// round 6
// speedup vs baseline: 4.3867x; 1.2802x over previous
#include <cuda_runtime.h>
#include <cuda_bf16.h>
#include <cuda_fp16.h>
#include <math.h>
#include <stdint.h>

#define BB 2
#define TT 2048
#define DIM 4096
#define NH 32
#define NKV 8
#define HD 128
#define MTOK (BB * TT)
#define GK 4096

// ---------------- device scratch ---------------------------------------
__device__ __align__(16) float g_q[(size_t)MTOK * NH * HD];
__device__ __align__(16) float g_k[(size_t)MTOK * NKV * HD];
__device__ __align__(16) float g_v[(size_t)MTOK * NKV * HD];

// fp16 GEMM operands: activations split hi/lo, weights hi only
__device__ __align__(16) __half g_xh[(size_t)MTOK * DIM];
__device__ __align__(16) __half g_xl[(size_t)MTOK * DIM];
__device__ __align__(16) __half g_wq[(size_t)DIM * DIM];
__device__ __align__(16) __half g_wk[(size_t)NKV * HD * DIM];
__device__ __align__(16) __half g_wv[(size_t)NKV * HD * DIM];
__device__ __align__(16) __half g_wo[(size_t)DIM * DIM];
__device__ __align__(16) __half g_ch[(size_t)MTOK * DIM];
__device__ __align__(16) __half g_cl[(size_t)MTOK * DIM];

// head-major fp16 q/k/v for flash
__device__ __align__(16) __half g_fqh[(size_t)BB * NH * TT * HD];
__device__ __align__(16) __half g_fql[(size_t)BB * NH * TT * HD];
__device__ __align__(16) __half g_fkh[(size_t)BB * NKV * TT * HD];
__device__ __align__(16) __half g_fkl[(size_t)BB * NKV * TT * HD];
__device__ __align__(16) __half g_fv [(size_t)BB * NKV * TT * HD];

// ---------------- helpers ----------------------------------------------
__device__ __forceinline__ uint32_t smem_u32(const void* p) {
    uint32_t a;
    asm("{ .reg .u64 t; cvta.to.shared.u64 t, %1; cvt.u32.u64 %0, t; }"
        : "=r"(a) : "l"(p));
    return a;
}
__device__ __forceinline__ void cpa16(uint32_t dst, const void* src) {
    asm volatile("cp.async.cg.shared.global [%0], [%1], 16;"
                 :: "r"(dst), "l"(src) : "memory");
}
__device__ __forceinline__ void cp_commit() {
    asm volatile("cp.async.commit_group;" ::: "memory");
}
__device__ __forceinline__ void cp_wait1() {
    asm volatile("cp.async.wait_group 1;" ::: "memory");
}
__device__ __forceinline__ void cp_wait0() {
    asm volatile("cp.async.wait_group 0;" ::: "memory");
}
__device__ __forceinline__ void ldsm4(uint32_t* r, uint32_t addr) {
    asm volatile("ldmatrix.sync.aligned.m8n8.x4.shared.b16 {%0,%1,%2,%3}, [%4];"
                 : "=r"(r[0]), "=r"(r[1]), "=r"(r[2]), "=r"(r[3]) : "r"(addr));
}
__device__ __forceinline__ void ldsm4t(uint32_t* r, uint32_t addr) {
    asm volatile("ldmatrix.sync.aligned.m8n8.x4.trans.shared.b16 {%0,%1,%2,%3}, [%4];"
                 : "=r"(r[0]), "=r"(r[1]), "=r"(r[2]), "=r"(r[3]) : "r"(addr));
}
__device__ __forceinline__ void mma_f16(float* d, const uint32_t* a, const uint32_t* b) {
    asm volatile(
        "mma.sync.aligned.m16n8k16.row.col.f32.f16.f16.f32 "
        "{%0,%1,%2,%3}, {%4,%5,%6,%7}, {%8,%9}, {%0,%1,%2,%3};\n"
        : "+f"(d[0]), "+f"(d[1]), "+f"(d[2]), "+f"(d[3])
        : "r"(a[0]), "r"(a[1]), "r"(a[2]), "r"(a[3]), "r"(b[0]), "r"(b[1]));
}
__device__ __forceinline__ uint32_t pack_h2(float lo, float hi) {
    __half2 h = __floats2half2_rn(lo, hi);
    return *(uint32_t*)&h;
}

// ---------------- prepacks -----------------------------------------------
__global__ void prep_f16_2(const float* __restrict__ s,
                           __half* __restrict__ h,
                           __half* __restrict__ l, int n) {
    int i = blockIdx.x * blockDim.x + threadIdx.x;
    if (i < n) {
        float x = s[i];
        __half hb = __float2half_rn(x);
        h[i] = hb;
        l[i] = __float2half_rn(x - __half2float(hb));
    }
}
__global__ void prep_f16_1(const float* __restrict__ s,
                           __half* __restrict__ h, int n) {
    int i = blockIdx.x * blockDim.x + threadIdx.x;
    if (i < n) h[i] = __float2half_rn(s[i]);
}

// ---------------- HMMA fp16x2 GEMM: C[M,N] = (Ah+Al) @ Bh^T --------------
#define BKC 32
#define ROWB 80
#define MAT_BYTES (128 * ROWB)         // 10240
#define STAGE_BYTES (3 * MAT_BYTES)    // 30720
#define GNC (GK / BKC)                 // 128

__global__ __launch_bounds__(256, 1)
void gemm_f16x2(const __half* __restrict__ Ah,
                const __half* __restrict__ Al,
                const __half* __restrict__ Bh,
                float* __restrict__ C, int N) {
    extern __shared__ char sm[];
    const uint32_t sbase = smem_u32(sm);
    const int tid  = threadIdx.x;
    const int lane = tid & 31;
    const int wid  = tid >> 5;
    const int wm   = wid >> 2;
    const int wn   = wid & 3;
    const int bm   = blockIdx.y * 128;
    const int bn   = blockIdx.x * 128;

    const __half* mats[3] = {Ah, Al, Bh};

    float d[4][4][4];
#pragma unroll
    for (int i = 0; i < 4; i++)
#pragma unroll
        for (int j = 0; j < 4; j++)
#pragma unroll
            for (int r = 0; r < 4; r++) d[i][j][r] = 0.f;

    // per stage: 3 mats x 128 rows x 4 chunks = 1536 16B chunks, 6/thread
    auto load_chunk = [&](int buf, int c) {
        const int kofs = c * BKC;
        const uint32_t base = sbase + buf * STAGE_BYTES;
#pragma unroll
        for (int t = 0; t < 6; t++) {
            int i   = tid + t * 256;
            int mat = i >> 9;
            int idx = i & 511;
            int row = idx >> 2;
            int ch  = idx & 3;
            int grow = ((mat < 2) ? bm : bn) + row;
            cpa16(base + mat * MAT_BYTES + row * ROWB + ch * 16,
                  mats[mat] + (size_t)grow * GK + kofs + ch * 8);
        }
    };

    load_chunk(0, 0); cp_commit();
    load_chunk(1, 1); cp_commit();

    const uint32_t a_off =
        (uint32_t)((wm * 64 + (lane & 15)) * ROWB + (lane >> 4) * 16);
    const uint32_t b_off = (uint32_t)(2 * MAT_BYTES +
        (wn * 32 + (lane & 7) + ((lane >> 4) & 1) * 8) * ROWB +
        ((lane >> 3) & 1) * 16);

    for (int c = 0; c < GNC; ++c) {
        if (c + 1 < GNC) cp_wait1(); else cp_wait0();
        __syncthreads();
        if (c + 2 < GNC) { load_chunk((c + 2) % 3, c + 2); cp_commit(); }

        const uint32_t stg = sbase + (c % 3) * STAGE_BYTES;
#pragma unroll
        for (int ks = 0; ks < 2; ks++) {
            uint32_t ah[4][4], al[4][4], bh[2][4];
#pragma unroll
            for (int i = 0; i < 4; i++)
                ldsm4(ah[i], stg + a_off + i * (16 * ROWB) + ks * 32);
#pragma unroll
            for (int i = 0; i < 4; i++)
                ldsm4(al[i], stg + MAT_BYTES + a_off + i * (16 * ROWB) + ks * 32);
#pragma unroll
            for (int jj = 0; jj < 2; jj++)
                ldsm4(bh[jj], stg + b_off + jj * (16 * ROWB) + ks * 32);

#pragma unroll
            for (int i = 0; i < 4; i++)
#pragma unroll
                for (int j = 0; j < 4; j++) {
                    const uint32_t* ph = &bh[j >> 1][(j & 1) * 2];
                    mma_f16(d[i][j], ah[i], ph);
                    mma_f16(d[i][j], al[i], ph);
                }
        }
    }

    const int r0 = bm + wm * 64 + (lane >> 2);
    const int c0 = bn + wn * 32 + (lane & 3) * 2;
#pragma unroll
    for (int i = 0; i < 4; i++)
#pragma unroll
        for (int j = 0; j < 4; j++) {
            int row = r0 + i * 16;
            int col = c0 + j * 8;
            *(float2*)&C[(size_t)row * N + col] =
                make_float2(d[i][j][0], d[i][j][1]);
            *(float2*)&C[(size_t)(row + 8) * N + col] =
                make_float2(d[i][j][2], d[i][j][3]);
        }
}

// ---------------- rope + fp16 pack (head-major) -------------------------
#define NQP (BB * NH * TT * (HD / 2))    // 8388608
#define NKP (BB * NKV * TT * (HD / 2))   // 2097152
#define NVE (BB * NKV * TT * HD)         // 4194304
__global__ void rope_pack(const float* __restrict__ fc, const float* __restrict__ fs) {
    int i = blockIdx.x * blockDim.x + threadIdx.x;
    if (i < NQP) {
        int dp = i & 63, t = (i >> 6) & 2047, hh = (i >> 17) & 31, b = i >> 22;
        size_t src = (((size_t)(b * TT + t) * NH + hh) << 7) + 2 * dp;
        float c = fc[t * 64 + dp], s = fs[t * 64 + dp];
        float xr = g_q[src], xi = g_q[src + 1];
        float o0 = xr * c - xi * s;
        float o1 = xr * s + xi * c;
        size_t dst = (((size_t)(b * NH + hh) * TT + t) << 7) + 2 * dp;
        __half h0 = __float2half_rn(o0), h1 = __float2half_rn(o1);
        g_fqh[dst] = h0;     g_fqh[dst + 1] = h1;
        g_fql[dst]     = __float2half_rn(o0 - __half2float(h0));
        g_fql[dst + 1] = __float2half_rn(o1 - __half2float(h1));
    } else if (i < NQP + NKP) {
        int j = i - NQP;
        int dp = j & 63, t = (j >> 6) & 2047, hh = (j >> 17) & 7, b = j >> 20;
        size_t src = (((size_t)(b * TT + t) * NKV + hh) << 7) + 2 * dp;
        float c = fc[t * 64 + dp], s = fs[t * 64 + dp];
        float xr = g_k[src], xi = g_k[src + 1];
        float o0 = xr * c - xi * s;
        float o1 = xr * s + xi * c;
        size_t dst = (((size_t)(b * NKV + hh) * TT + t) << 7) + 2 * dp;
        __half h0 = __float2half_rn(o0), h1 = __float2half_rn(o1);
        g_fkh[dst] = h0;     g_fkh[dst + 1] = h1;
        g_fkl[dst]     = __float2half_rn(o0 - __half2float(h0));
        g_fkl[dst + 1] = __float2half_rn(o1 - __half2float(h1));
    } else if (i < NQP + NKP + NVE) {
        int e = i - NQP - NKP;
        int dd = e & 127, t = (e >> 7) & 2047, hh = (e >> 18) & 7, b = e >> 21;
        size_t src = (((size_t)(b * TT + t) * NKV + hh) << 7) + dd;
        size_t dst = (((size_t)(b * NKV + hh) * TT + t) << 7) + dd;
        g_fv[dst] = __float2half_rn(g_v[src]);
    }
}

// ---------------- flash attention: fp16 HMMA, FA2 register softmax -----
#define FSTG 65536
#define FSTGB 49152
#define FSMEM (FSTG + 2 * FSTGB)        // 163840
#define NSTILE (TT / 64)                // 32

__global__ __launch_bounds__(256, 1)
void flash_hmma(const __half* __restrict__ Qh, const __half* __restrict__ Ql,
                const __half* __restrict__ Kh, const __half* __restrict__ Kl,
                const __half* __restrict__ Vv,
                __half* __restrict__ Ch, __half* __restrict__ Cl) {
    extern __shared__ char sm[];
    const uint32_t sb = smem_u32(sm);
    const int tid = threadIdx.x, lane = tid & 31, w = tid >> 5;
    const int t0 = blockIdx.x * 128;
    const int h  = blockIdx.y;
    const int b  = blockIdx.z;
    const int kh = h & 7;

    const __half* qhp = Qh + (((size_t)(b * NH + h) * TT + t0) << 7);
    const __half* qlp = Ql + (((size_t)(b * NH + h) * TT + t0) << 7);
    const __half* khp = Kh + (((size_t)(b * NKV + kh) * TT) << 7);
    const __half* klp = Kl + (((size_t)(b * NKV + kh) * TT) << 7);
    const __half* vhp = Vv + (((size_t)(b * NKV + kh) * TT) << 7);

    // Q tile hi/lo: 128 rows x 16 chunks x 2 arrays = 4096 16B chunks
#pragma unroll
    for (int it = 0; it < 16; it++) {
        int i = tid + it * 256;
        int arr = i >> 11, ci = i & 2047;
        int r = ci >> 4, c = ci & 15;
        cpa16(sb + arr * 32768 + r * 256 + ((c ^ (r & 7)) * 16),
              (arr ? qlp : qhp) + r * HD + c * 8);
    }
    cp_commit();

    auto load_kv = [&](int stg, int s) {
        const uint32_t bs = sb + FSTG + stg * FSTGB;
        const __half* srcs[3] = {khp + (size_t)s * 64 * HD,
                                 klp + (size_t)s * 64 * HD,
                                 vhp + (size_t)s * 64 * HD};
#pragma unroll
        for (int it = 0; it < 12; it++) {
            int i = tid + it * 256;
            int arr = i >> 10, ci = i & 1023;
            int r = ci >> 4, c = ci & 15;
            cpa16(bs + arr * 16384 + r * 256 + ((c ^ (r & 7)) * 16),
                  srcs[arr] + r * HD + c * 8);
        }
    };
    load_kv(0, 0); cp_commit();
    load_kv(1, 1); cp_commit();

    float oa[16][4];
#pragma unroll
    for (int nt = 0; nt < 16; nt++)
#pragma unroll
        for (int c = 0; c < 4; c++) oa[nt][c] = 0.f;
    float m0 = -1e30f, m1 = -1e30f, l0 = 0.f, l1 = 0.f;
    const float scale = 0.08838834764831845f;

    const int qr = w * 16 + (lane & 15);
    const uint32_t qrow = sb + qr * 256;
    const int kr = (lane & 7) + ((lane >> 4) & 1) * 8;
    const int vr = lane & 15;

    for (int s = 0; s < NSTILE; s++) {
        if (s + 1 < NSTILE) cp_wait1(); else cp_wait0();
        __syncthreads();
        const uint32_t kb = sb + FSTG + (s & 1) * FSTGB;

        // ---- S = Q K^T (fp16 3-pass) ----
        float sa[8][4];
#pragma unroll
        for (int j = 0; j < 8; j++)
#pragma unroll
            for (int c = 0; c < 4; c++) sa[j][c] = 0.f;

#pragma unroll
        for (int kc = 0; kc < 8; kc++) {
            uint32_t qa[4], qb[4];
            {
                int c = 2 * kc + (lane >> 4);
                uint32_t a = qrow + ((c ^ (qr & 7)) * 16);
                ldsm4(qa, a);
                ldsm4(qb, a + 32768);
            }
#pragma unroll
            for (int kt = 0; kt < 4; kt++) {
                uint32_t kfh[4], kfl[4];
                int krr = kt * 16 + kr;
                int kcc = 2 * kc + ((lane >> 3) & 1);
                uint32_t ka = kb + krr * 256 + ((kcc ^ (krr & 7)) * 16);
                ldsm4(kfh, ka);
                ldsm4(kfl, ka + 16384);
#pragma unroll
                for (int hn = 0; hn < 2; hn++) {
                    int j = kt * 2 + hn;
                    mma_f16(sa[j], qa, &kfh[hn * 2]);
                    mma_f16(sa[j], qa, &kfl[hn * 2]);
                    mma_f16(sa[j], qb, &kfh[hn * 2]);
                }
            }
        }

        // ---- online softmax (registers) ----
        float mx0 = -1e30f, mx1 = -1e30f;
#pragma unroll
        for (int j = 0; j < 8; j++) {
#pragma unroll
            for (int c = 0; c < 4; c++) sa[j][c] *= scale;
            mx0 = fmaxf(mx0, fmaxf(sa[j][0], sa[j][1]));
            mx1 = fmaxf(mx1, fmaxf(sa[j][2], sa[j][3]));
        }
#pragma unroll
        for (int off = 1; off <= 2; off <<= 1) {
            mx0 = fmaxf(mx0, __shfl_xor_sync(0xffffffffu, mx0, off));
            mx1 = fmaxf(mx1, __shfl_xor_sync(0xffffffffu, mx1, off));
        }
        float nm0 = fmaxf(m0, mx0), nm1 = fmaxf(m1, mx1);
        float al0 = __expf(m0 - nm0), al1 = __expf(m1 - nm1);
        float rs0 = 0.f, rs1 = 0.f;
#pragma unroll
        for (int j = 0; j < 8; j++) {
            sa[j][0] = __expf(sa[j][0] - nm0);
            sa[j][1] = __expf(sa[j][1] - nm0);
            sa[j][2] = __expf(sa[j][2] - nm1);
            sa[j][3] = __expf(sa[j][3] - nm1);
            rs0 += sa[j][0] + sa[j][1];
            rs1 += sa[j][2] + sa[j][3];
        }
#pragma unroll
        for (int off = 1; off <= 2; off <<= 1) {
            rs0 += __shfl_xor_sync(0xffffffffu, rs0, off);
            rs1 += __shfl_xor_sync(0xffffffffu, rs1, off);
        }
        l0 = l0 * al0 + rs0;  l1 = l1 * al1 + rs1;
        m0 = nm0;  m1 = nm1;
#pragma unroll
        for (int nt = 0; nt < 16; nt++) {
            oa[nt][0] *= al0; oa[nt][1] *= al0;
            oa[nt][2] *= al1; oa[nt][3] *= al1;
        }

        // ---- O += P V ----
#pragma unroll
        for (int kc2 = 0; kc2 < 4; kc2++) {
            uint32_t pa[4];
            pa[0] = pack_h2(sa[2 * kc2][0],     sa[2 * kc2][1]);
            pa[1] = pack_h2(sa[2 * kc2][2],     sa[2 * kc2][3]);
            pa[2] = pack_h2(sa[2 * kc2 + 1][0], sa[2 * kc2 + 1][1]);
            pa[3] = pack_h2(sa[2 * kc2 + 1][2], sa[2 * kc2 + 1][3]);
            int vrr = kc2 * 16 + vr;
            uint32_t vrow = kb + 32768 + vrr * 256;
#pragma unroll
            for (int nt2 = 0; nt2 < 8; nt2++) {
                uint32_t vf[4];
                int vc = nt2 * 2 + (lane >> 4);
                ldsm4t(vf, vrow + ((vc ^ (vrr & 7)) * 16));
                mma_f16(oa[nt2 * 2],     pa, &vf[0]);
                mma_f16(oa[nt2 * 2 + 1], pa, &vf[2]);
            }
        }

        __syncthreads();
        if (s + 2 < NSTILE) { load_kv(s & 1, s + 2); cp_commit(); }
    }

    // ---- epilogue: normalize, split fp16 hi/lo, store ctx --------------
    float i0 = 1.f / l0, i1 = 1.f / l1;
    int rg0 = t0 + w * 16 + (lane >> 2);
    size_t row0 = (size_t)(b * TT + rg0) * DIM;
    size_t row1 = row0 + 8 * DIM;
#pragma unroll
    for (int nt = 0; nt < 16; nt++) {
        int col = h * HD + nt * 8 + (lane & 3) * 2;
        {
            float f0 = oa[nt][0] * i0, f1 = oa[nt][1] * i0;
            __half h0 = __float2half_rn(f0), h1 = __float2half_rn(f1);
            __half2 hv; hv.x = h0; hv.y = h1;
            *(uint32_t*)(Ch + row0 + col) = *(uint32_t*)&hv;
            __half2 lv;
            lv.x = __float2half_rn(f0 - __half2float(h0));
            lv.y = __float2half_rn(f1 - __half2float(h1));
            *(uint32_t*)(Cl + row0 + col) = *(uint32_t*)&lv;
        }
        {
            float f0 = oa[nt][2] * i1, f1 = oa[nt][3] * i1;
            __half h0 = __float2half_rn(f0), h1 = __float2half_rn(f1);
            __half2 hv; hv.x = h0; hv.y = h1;
            *(uint32_t*)(Ch + row1 + col) = *(uint32_t*)&hv;
            __half2 lv;
            lv.x = __float2half_rn(f0 - __half2float(h0));
            lv.y = __float2half_rn(f1 - __half2float(h1));
            *(uint32_t*)(Cl + row1 + col) = *(uint32_t*)&lv;
        }
    }
}

// ---------------------------------------------------------------------------
extern "C" void kernel_launch(void* const* d_in, const int* in_sizes, int n_in,
                              void* d_out, int out_size) {
    const float* x  = (const float*)d_in[0];
    const float* wq = (const float*)d_in[1];
    const float* wk = (const float*)d_in[2];
    const float* wv = (const float*)d_in[3];
    const float* wo = (const float*)d_in[4];
    const float* fc = (const float*)d_in[5];
    const float* fs = (const float*)d_in[6];
    float* out = (float*)d_out;

    float *qp, *kp, *vp;
    cudaGetSymbolAddress((void**)&qp, g_q);
    cudaGetSymbolAddress((void**)&kp, g_k);
    cudaGetSymbolAddress((void**)&vp, g_v);
    __half *xh, *xl, *wqp, *wkp, *wvp, *wop, *ch, *cl;
    cudaGetSymbolAddress((void**)&xh,  g_xh);  cudaGetSymbolAddress((void**)&xl,  g_xl);
    cudaGetSymbolAddress((void**)&wqp, g_wq);  cudaGetSymbolAddress((void**)&wkp, g_wk);
    cudaGetSymbolAddress((void**)&wvp, g_wv);  cudaGetSymbolAddress((void**)&wop, g_wo);
    cudaGetSymbolAddress((void**)&ch,  g_ch);  cudaGetSymbolAddress((void**)&cl,  g_cl);
    __half *fqh, *fql, *fkh, *fkl, *fv;
    cudaGetSymbolAddress((void**)&fqh, g_fqh); cudaGetSymbolAddress((void**)&fql, g_fql);
    cudaGetSymbolAddress((void**)&fkh, g_fkh); cudaGetSymbolAddress((void**)&fkl, g_fkl);
    cudaGetSymbolAddress((void**)&fv,  g_fv);

    const int NBIG = MTOK * DIM;
    const int NKW  = NKV * HD * DIM;

    prep_f16_2<<<(NBIG + 255) / 256, 256>>>(x, xh, xl, NBIG);
    prep_f16_1<<<(NBIG + 255) / 256, 256>>>(wq, wqp, NBIG);
    prep_f16_1<<<(NKW  + 255) / 256, 256>>>(wk, wkp, NKW);
    prep_f16_1<<<(NKW  + 255) / 256, 256>>>(wv, wvp, NKW);
    prep_f16_1<<<(NBIG + 255) / 256, 256>>>(wo, wop, NBIG);

    const int GEMM_SMEM = 3 * STAGE_BYTES;   // 92160
    cudaFuncSetAttribute(gemm_f16x2,
                         cudaFuncAttributeMaxDynamicSharedMemorySize, GEMM_SMEM);

    gemm_f16x2<<<dim3(DIM / 128, MTOK / 128), 256, GEMM_SMEM>>>(xh, xl, wqp, qp, DIM);
    gemm_f16x2<<<dim3((NKV * HD) / 128, MTOK / 128), 256, GEMM_SMEM>>>(xh, xl, wkp, kp, NKV * HD);
    gemm_f16x2<<<dim3((NKV * HD) / 128, MTOK / 128), 256, GEMM_SMEM>>>(xh, xl, wvp, vp, NKV * HD);

    {
        int total = NQP + NKP + NVE;
        rope_pack<<<(total + 255) / 256, 256>>>(fc, fs);
    }

    cudaFuncSetAttribute(flash_hmma,
                         cudaFuncAttributeMaxDynamicSharedMemorySize, FSMEM);
    flash_hmma<<<dim3(TT / 128, NH, BB), 256, FSMEM>>>(fqh, fql, fkh, fkl, fv, ch, cl);

    gemm_f16x2<<<dim3(DIM / 128, MTOK / 128), 256, GEMM_SMEM>>>(ch, cl, wop, out, DIM);
}

// round 7
// speedup vs baseline: 5.4352x; 1.2390x over previous
#include <cuda_runtime.h>
#include <cuda_bf16.h>
#include <cuda_fp16.h>
#include <math.h>
#include <stdint.h>

#define BB 2
#define TT 2048
#define DIM 4096
#define NH 32
#define NKV 8
#define HD 128
#define MTOK (BB * TT)
#define GK 4096
#define NQKV (DIM + 2 * NKV * HD)   // 5120

// ---------------- device scratch ---------------------------------------
__device__ __align__(16) float g_qkv[(size_t)MTOK * NQKV];   // q|k|v fused

__device__ __align__(16) __half g_xh[(size_t)MTOK * DIM];
__device__ __align__(16) __half g_xl[(size_t)MTOK * DIM];
__device__ __align__(16) __half g_wqkv[(size_t)NQKV * DIM];  // wq|wk|wv
__device__ __align__(16) __half g_wo[(size_t)DIM * DIM];
__device__ __align__(16) __half g_ch[(size_t)MTOK * DIM];
__device__ __align__(16) __half g_cl[(size_t)MTOK * DIM];

// head-major fp16 q/k/v for flash
__device__ __align__(16) __half g_fqh[(size_t)BB * NH * TT * HD];
__device__ __align__(16) __half g_fql[(size_t)BB * NH * TT * HD];
__device__ __align__(16) __half g_fkh[(size_t)BB * NKV * TT * HD];
__device__ __align__(16) __half g_fkl[(size_t)BB * NKV * TT * HD];
__device__ __align__(16) __half g_fv [(size_t)BB * NKV * TT * HD];

// ---------------- helpers ----------------------------------------------
__device__ __forceinline__ uint32_t smem_u32(const void* p) {
    uint32_t a;
    asm("{ .reg .u64 t; cvta.to.shared.u64 t, %1; cvt.u32.u64 %0, t; }"
        : "=r"(a) : "l"(p));
    return a;
}
__device__ __forceinline__ void cpa16(uint32_t dst, const void* src) {
    asm volatile("cp.async.cg.shared.global [%0], [%1], 16;"
                 :: "r"(dst), "l"(src) : "memory");
}
__device__ __forceinline__ void cp_commit() {
    asm volatile("cp.async.commit_group;" ::: "memory");
}
__device__ __forceinline__ void cp_wait1() {
    asm volatile("cp.async.wait_group 1;" ::: "memory");
}
__device__ __forceinline__ void cp_wait0() {
    asm volatile("cp.async.wait_group 0;" ::: "memory");
}
__device__ __forceinline__ void ldsm4(uint32_t* r, uint32_t addr) {
    asm volatile("ldmatrix.sync.aligned.m8n8.x4.shared.b16 {%0,%1,%2,%3}, [%4];"
                 : "=r"(r[0]), "=r"(r[1]), "=r"(r[2]), "=r"(r[3]) : "r"(addr));
}
__device__ __forceinline__ void ldsm4t(uint32_t* r, uint32_t addr) {
    asm volatile("ldmatrix.sync.aligned.m8n8.x4.trans.shared.b16 {%0,%1,%2,%3}, [%4];"
                 : "=r"(r[0]), "=r"(r[1]), "=r"(r[2]), "=r"(r[3]) : "r"(addr));
}
__device__ __forceinline__ void mma_f16(float* d, const uint32_t* a, const uint32_t* b) {
    asm volatile(
        "mma.sync.aligned.m16n8k16.row.col.f32.f16.f16.f32 "
        "{%0,%1,%2,%3}, {%4,%5,%6,%7}, {%8,%9}, {%0,%1,%2,%3};\n"
        : "+f"(d[0]), "+f"(d[1]), "+f"(d[2]), "+f"(d[3])
        : "r"(a[0]), "r"(a[1]), "r"(a[2]), "r"(a[3]), "r"(b[0]), "r"(b[1]));
}
__device__ __forceinline__ uint32_t pack_h2(float lo, float hi) {
    __half2 h = __floats2half2_rn(lo, hi);
    return *(uint32_t*)&h;
}

// ---------------- prepacks -----------------------------------------------
__global__ void prep_f16_2(const float* __restrict__ s,
                           __half* __restrict__ h,
                           __half* __restrict__ l, int n) {
    int i = blockIdx.x * blockDim.x + threadIdx.x;
    if (i < n) {
        float x = s[i];
        __half hb = __float2half_rn(x);
        h[i] = hb;
        l[i] = __float2half_rn(x - __half2float(hb));
    }
}
__global__ void prep_f16_1(const float* __restrict__ s,
                           __half* __restrict__ h, int n) {
    int i = blockIdx.x * blockDim.x + threadIdx.x;
    if (i < n) h[i] = __float2half_rn(s[i]);
}

// ---------------- HMMA fp16x2 GEMM: C[M,N] = (Ah+Al) @ Bh^T --------------
// BKC=64, 2 stages, 2 CTAs/SM. smem/CTA = 2*3*128*144 = 110592 B.
#define BKC 64
#define ROWB 144
#define MAT_BYTES (128 * ROWB)         // 18432
#define STAGE_BYTES (3 * MAT_BYTES)    // 55296
#define GNC (GK / BKC)                 // 64
#define GEMM_SMEM (2 * STAGE_BYTES)    // 110592

__global__ __launch_bounds__(256, 2)
void gemm_f16x2(const __half* __restrict__ Ah,
                const __half* __restrict__ Al,
                const __half* __restrict__ Bh,
                float* __restrict__ C, int N) {
    extern __shared__ char sm[];
    const uint32_t sbase = smem_u32(sm);
    const int tid  = threadIdx.x;
    const int lane = tid & 31;
    const int wid  = tid >> 5;
    const int wm   = wid >> 2;
    const int wn   = wid & 3;
    const int bm   = blockIdx.y * 128;
    const int bn   = blockIdx.x * 128;

    const __half* mats[3] = {Ah, Al, Bh};

    float d[4][4][4];
#pragma unroll
    for (int i = 0; i < 4; i++)
#pragma unroll
        for (int j = 0; j < 4; j++)
#pragma unroll
            for (int r = 0; r < 4; r++) d[i][j][r] = 0.f;

    // per stage: 3 mats x 128 rows x 8 chunks = 3072 16B chunks, 12/thread
    auto load_chunk = [&](int buf, int c) {
        const int kofs = c * BKC;
        const uint32_t base = sbase + buf * STAGE_BYTES;
#pragma unroll
        for (int t = 0; t < 12; t++) {
            int i   = tid + t * 256;
            int mat = i >> 10;
            int idx = i & 1023;
            int row = idx >> 3;
            int ch  = idx & 7;
            int grow = ((mat < 2) ? bm : bn) + row;
            cpa16(base + mat * MAT_BYTES + row * ROWB + ch * 16,
                  mats[mat] + (size_t)grow * GK + kofs + ch * 8);
        }
    };

    load_chunk(0, 0); cp_commit();

    const uint32_t a_off =
        (uint32_t)((wm * 64 + (lane & 15)) * ROWB + (lane >> 4) * 16);
    const uint32_t b_off = (uint32_t)(2 * MAT_BYTES +
        (wn * 32 + (lane & 7) + ((lane >> 4) & 1) * 8) * ROWB +
        ((lane >> 3) & 1) * 16);

    for (int c = 0; c < GNC; ++c) {
        const int b = c & 1;
        if (c + 1 < GNC) {
            load_chunk(b ^ 1, c + 1);
            cp_commit();
            cp_wait1();
        } else {
            cp_wait0();
        }
        __syncthreads();

        const uint32_t stg = sbase + b * STAGE_BYTES;
#pragma unroll
        for (int ks = 0; ks < 4; ks++) {
            uint32_t ah[4][4], al[4][4], bh[2][4];
#pragma unroll
            for (int i = 0; i < 4; i++)
                ldsm4(ah[i], stg + a_off + i * (16 * ROWB) + ks * 32);
#pragma unroll
            for (int i = 0; i < 4; i++)
                ldsm4(al[i], stg + MAT_BYTES + a_off + i * (16 * ROWB) + ks * 32);
#pragma unroll
            for (int jj = 0; jj < 2; jj++)
                ldsm4(bh[jj], stg + b_off + jj * (16 * ROWB) + ks * 32);

#pragma unroll
            for (int i = 0; i < 4; i++)
#pragma unroll
                for (int j = 0; j < 4; j++) {
                    const uint32_t* ph = &bh[j >> 1][(j & 1) * 2];
                    mma_f16(d[i][j], ah[i], ph);
                    mma_f16(d[i][j], al[i], ph);
                }
        }
        __syncthreads();
    }

    const int r0 = bm + wm * 64 + (lane >> 2);
    const int c0 = bn + wn * 32 + (lane & 3) * 2;
#pragma unroll
    for (int i = 0; i < 4; i++)
#pragma unroll
        for (int j = 0; j < 4; j++) {
            int row = r0 + i * 16;
            int col = c0 + j * 8;
            *(float2*)&C[(size_t)row * N + col] =
                make_float2(d[i][j][0], d[i][j][1]);
            *(float2*)&C[(size_t)(row + 8) * N + col] =
                make_float2(d[i][j][2], d[i][j][3]);
        }
}

// ---------------- rope + fp16 pack (head-major), reads fused qkv --------
#define NQP (BB * NH * TT * (HD / 2))    // 8388608
#define NKP (BB * NKV * TT * (HD / 2))   // 2097152
#define NVE (BB * NKV * TT * HD)         // 4194304
__global__ void rope_pack(const float* __restrict__ fc, const float* __restrict__ fs) {
    int i = blockIdx.x * blockDim.x + threadIdx.x;
    if (i < NQP) {
        int dp = i & 63, t = (i >> 6) & 2047, hh = (i >> 17) & 31, b = i >> 22;
        size_t src = (size_t)(b * TT + t) * NQKV + hh * HD + 2 * dp;
        float c = fc[t * 64 + dp], s = fs[t * 64 + dp];
        float xr = g_qkv[src], xi = g_qkv[src + 1];
        float o0 = xr * c - xi * s;
        float o1 = xr * s + xi * c;
        size_t dst = (((size_t)(b * NH + hh) * TT + t) << 7) + 2 * dp;
        __half h0 = __float2half_rn(o0), h1 = __float2half_rn(o1);
        g_fqh[dst] = h0;     g_fqh[dst + 1] = h1;
        g_fql[dst]     = __float2half_rn(o0 - __half2float(h0));
        g_fql[dst + 1] = __float2half_rn(o1 - __half2float(h1));
    } else if (i < NQP + NKP) {
        int j = i - NQP;
        int dp = j & 63, t = (j >> 6) & 2047, hh = (j >> 17) & 7, b = j >> 20;
        size_t src = (size_t)(b * TT + t) * NQKV + DIM + hh * HD + 2 * dp;
        float c = fc[t * 64 + dp], s = fs[t * 64 + dp];
        float xr = g_qkv[src], xi = g_qkv[src + 1];
        float o0 = xr * c - xi * s;
        float o1 = xr * s + xi * c;
        size_t dst = (((size_t)(b * NKV + hh) * TT + t) << 7) + 2 * dp;
        __half h0 = __float2half_rn(o0), h1 = __float2half_rn(o1);
        g_fkh[dst] = h0;     g_fkh[dst + 1] = h1;
        g_fkl[dst]     = __float2half_rn(o0 - __half2float(h0));
        g_fkl[dst + 1] = __float2half_rn(o1 - __half2float(h1));
    } else if (i < NQP + NKP + NVE) {
        int e = i - NQP - NKP;
        int dd = e & 127, t = (e >> 7) & 2047, hh = (e >> 18) & 7, b = e >> 21;
        size_t src = (size_t)(b * TT + t) * NQKV + DIM + NKV * HD + hh * HD + dd;
        size_t dst = (((size_t)(b * NKV + hh) * TT + t) << 7) + dd;
        g_fv[dst] = __float2half_rn(g_qkv[src]);
    }
}

// ---------------- flash attention: fp16 HMMA, FA2 register softmax -----
#define FSTG 65536
#define FSTGB 49152
#define FSMEM (FSTG + 2 * FSTGB)        // 163840
#define NSTILE (TT / 64)                // 32

__global__ __launch_bounds__(256, 1)
void flash_hmma(const __half* __restrict__ Qh, const __half* __restrict__ Ql,
                const __half* __restrict__ Kh, const __half* __restrict__ Kl,
                const __half* __restrict__ Vv,
                __half* __restrict__ Ch, __half* __restrict__ Cl) {
    extern __shared__ char sm[];
    const uint32_t sb = smem_u32(sm);
    const int tid = threadIdx.x, lane = tid & 31, w = tid >> 5;
    const int t0 = blockIdx.x * 128;
    const int h  = blockIdx.y;
    const int b  = blockIdx.z;
    const int kh = h & 7;

    const __half* qhp = Qh + (((size_t)(b * NH + h) * TT + t0) << 7);
    const __half* qlp = Ql + (((size_t)(b * NH + h) * TT + t0) << 7);
    const __half* khp = Kh + (((size_t)(b * NKV + kh) * TT) << 7);
    const __half* klp = Kl + (((size_t)(b * NKV + kh) * TT) << 7);
    const __half* vhp = Vv + (((size_t)(b * NKV + kh) * TT) << 7);

#pragma unroll
    for (int it = 0; it < 16; it++) {
        int i = tid + it * 256;
        int arr = i >> 11, ci = i & 2047;
        int r = ci >> 4, c = ci & 15;
        cpa16(sb + arr * 32768 + r * 256 + ((c ^ (r & 7)) * 16),
              (arr ? qlp : qhp) + r * HD + c * 8);
    }
    cp_commit();

    auto load_kv = [&](int stg, int s) {
        const uint32_t bs = sb + FSTG + stg * FSTGB;
        const __half* srcs[3] = {khp + (size_t)s * 64 * HD,
                                 klp + (size_t)s * 64 * HD,
                                 vhp + (size_t)s * 64 * HD};
#pragma unroll
        for (int it = 0; it < 12; it++) {
            int i = tid + it * 256;
            int arr = i >> 10, ci = i & 1023;
            int r = ci >> 4, c = ci & 15;
            cpa16(bs + arr * 16384 + r * 256 + ((c ^ (r & 7)) * 16),
                  srcs[arr] + r * HD + c * 8);
        }
    };
    load_kv(0, 0); cp_commit();
    load_kv(1, 1); cp_commit();

    float oa[16][4];
#pragma unroll
    for (int nt = 0; nt < 16; nt++)
#pragma unroll
        for (int c = 0; c < 4; c++) oa[nt][c] = 0.f;
    float m0 = -1e30f, m1 = -1e30f, l0 = 0.f, l1 = 0.f;
    const float scale = 0.08838834764831845f;

    const int qr = w * 16 + (lane & 15);
    const uint32_t qrow = sb + qr * 256;
    const int kr = (lane & 7) + ((lane >> 4) & 1) * 8;
    const int vr = lane & 15;

    for (int s = 0; s < NSTILE; s++) {
        if (s + 1 < NSTILE) cp_wait1(); else cp_wait0();
        __syncthreads();
        const uint32_t kb = sb + FSTG + (s & 1) * FSTGB;

        float sa[8][4];
#pragma unroll
        for (int j = 0; j < 8; j++)
#pragma unroll
            for (int c = 0; c < 4; c++) sa[j][c] = 0.f;

#pragma unroll
        for (int kc = 0; kc < 8; kc++) {
            uint32_t qa[4], qb[4];
            {
                int c = 2 * kc + (lane >> 4);
                uint32_t a = qrow + ((c ^ (qr & 7)) * 16);
                ldsm4(qa, a);
                ldsm4(qb, a + 32768);
            }
#pragma unroll
            for (int kt = 0; kt < 4; kt++) {
                uint32_t kfh[4], kfl[4];
                int krr = kt * 16 + kr;
                int kcc = 2 * kc + ((lane >> 3) & 1);
                uint32_t ka = kb + krr * 256 + ((kcc ^ (krr & 7)) * 16);
                ldsm4(kfh, ka);
                ldsm4(kfl, ka + 16384);
#pragma unroll
                for (int hn = 0; hn < 2; hn++) {
                    int j = kt * 2 + hn;
                    mma_f16(sa[j], qa, &kfh[hn * 2]);
                    mma_f16(sa[j], qa, &kfl[hn * 2]);
                    mma_f16(sa[j], qb, &kfh[hn * 2]);
                }
            }
        }

        float mx0 = -1e30f, mx1 = -1e30f;
#pragma unroll
        for (int j = 0; j < 8; j++) {
#pragma unroll
            for (int c = 0; c < 4; c++) sa[j][c] *= scale;
            mx0 = fmaxf(mx0, fmaxf(sa[j][0], sa[j][1]));
            mx1 = fmaxf(mx1, fmaxf(sa[j][2], sa[j][3]));
        }
#pragma unroll
        for (int off = 1; off <= 2; off <<= 1) {
            mx0 = fmaxf(mx0, __shfl_xor_sync(0xffffffffu, mx0, off));
            mx1 = fmaxf(mx1, __shfl_xor_sync(0xffffffffu, mx1, off));
        }
        float nm0 = fmaxf(m0, mx0), nm1 = fmaxf(m1, mx1);
        float al0 = __expf(m0 - nm0), al1 = __expf(m1 - nm1);
        float rs0 = 0.f, rs1 = 0.f;
#pragma unroll
        for (int j = 0; j < 8; j++) {
            sa[j][0] = __expf(sa[j][0] - nm0);
            sa[j][1] = __expf(sa[j][1] - nm0);
            sa[j][2] = __expf(sa[j][2] - nm1);
            sa[j][3] = __expf(sa[j][3] - nm1);
            rs0 += sa[j][0] + sa[j][1];
            rs1 += sa[j][2] + sa[j][3];
        }
#pragma unroll
        for (int off = 1; off <= 2; off <<= 1) {
            rs0 += __shfl_xor_sync(0xffffffffu, rs0, off);
            rs1 += __shfl_xor_sync(0xffffffffu, rs1, off);
        }
        l0 = l0 * al0 + rs0;  l1 = l1 * al1 + rs1;
        m0 = nm0;  m1 = nm1;
#pragma unroll
        for (int nt = 0; nt < 16; nt++) {
            oa[nt][0] *= al0; oa[nt][1] *= al0;
            oa[nt][2] *= al1; oa[nt][3] *= al1;
        }

#pragma unroll
        for (int kc2 = 0; kc2 < 4; kc2++) {
            uint32_t pa[4];
            pa[0] = pack_h2(sa[2 * kc2][0],     sa[2 * kc2][1]);
            pa[1] = pack_h2(sa[2 * kc2][2],     sa[2 * kc2][3]);
            pa[2] = pack_h2(sa[2 * kc2 + 1][0], sa[2 * kc2 + 1][1]);
            pa[3] = pack_h2(sa[2 * kc2 + 1][2], sa[2 * kc2 + 1][3]);
            int vrr = kc2 * 16 + vr;
            uint32_t vrow = kb + 32768 + vrr * 256;
#pragma unroll
            for (int nt2 = 0; nt2 < 8; nt2++) {
                uint32_t vf[4];
                int vc = nt2 * 2 + (lane >> 4);
                ldsm4t(vf, vrow + ((vc ^ (vrr & 7)) * 16));
                mma_f16(oa[nt2 * 2],     pa, &vf[0]);
                mma_f16(oa[nt2 * 2 + 1], pa, &vf[2]);
            }
        }

        __syncthreads();
        if (s + 2 < NSTILE) { load_kv(s & 1, s + 2); cp_commit(); }
    }

    float i0 = 1.f / l0, i1 = 1.f / l1;
    int rg0 = t0 + w * 16 + (lane >> 2);
    size_t row0 = (size_t)(b * TT + rg0) * DIM;
    size_t row1 = row0 + 8 * DIM;
#pragma unroll
    for (int nt = 0; nt < 16; nt++) {
        int col = h * HD + nt * 8 + (lane & 3) * 2;
        {
            float f0 = oa[nt][0] * i0, f1 = oa[nt][1] * i0;
            __half h0 = __float2half_rn(f0), h1 = __float2half_rn(f1);
            __half2 hv; hv.x = h0; hv.y = h1;
            *(uint32_t*)(Ch + row0 + col) = *(uint32_t*)&hv;
            __half2 lv;
            lv.x = __float2half_rn(f0 - __half2float(h0));
            lv.y = __float2half_rn(f1 - __half2float(h1));
            *(uint32_t*)(Cl + row0 + col) = *(uint32_t*)&lv;
        }
        {
            float f0 = oa[nt][2] * i1, f1 = oa[nt][3] * i1;
            __half h0 = __float2half_rn(f0), h1 = __float2half_rn(f1);
            __half2 hv; hv.x = h0; hv.y = h1;
            *(uint32_t*)(Ch + row1 + col) = *(uint32_t*)&hv;
            __half2 lv;
            lv.x = __float2half_rn(f0 - __half2float(h0));
            lv.y = __float2half_rn(f1 - __half2float(h1));
            *(uint32_t*)(Cl + row1 + col) = *(uint32_t*)&lv;
        }
    }
}

// ---------------------------------------------------------------------------
extern "C" void kernel_launch(void* const* d_in, const int* in_sizes, int n_in,
                              void* d_out, int out_size) {
    const float* x  = (const float*)d_in[0];
    const float* wq = (const float*)d_in[1];
    const float* wk = (const float*)d_in[2];
    const float* wv = (const float*)d_in[3];
    const float* wo = (const float*)d_in[4];
    const float* fc = (const float*)d_in[5];
    const float* fs = (const float*)d_in[6];
    float* out = (float*)d_out;

    float* qkv;
    cudaGetSymbolAddress((void**)&qkv, g_qkv);
    __half *xh, *xl, *wqkv, *wop, *ch, *cl;
    cudaGetSymbolAddress((void**)&xh,   g_xh);
    cudaGetSymbolAddress((void**)&xl,   g_xl);
    cudaGetSymbolAddress((void**)&wqkv, g_wqkv);
    cudaGetSymbolAddress((void**)&wop,  g_wo);
    cudaGetSymbolAddress((void**)&ch,   g_ch);
    cudaGetSymbolAddress((void**)&cl,   g_cl);
    __half *fqh, *fql, *fkh, *fkl, *fv;
    cudaGetSymbolAddress((void**)&fqh, g_fqh); cudaGetSymbolAddress((void**)&fql, g_fql);
    cudaGetSymbolAddress((void**)&fkh, g_fkh); cudaGetSymbolAddress((void**)&fkl, g_fkl);
    cudaGetSymbolAddress((void**)&fv,  g_fv);

    const int NBIG = MTOK * DIM;          // 16.7M
    const int NKW  = NKV * HD * DIM;      // 4.2M

    prep_f16_2<<<(NBIG + 255) / 256, 256>>>(x, xh, xl, NBIG);
    prep_f16_1<<<(NBIG + 255) / 256, 256>>>(wq, wqkv, NBIG);
    prep_f16_1<<<(NKW  + 255) / 256, 256>>>(wk, wqkv + (size_t)DIM * GK, NKW);
    prep_f16_1<<<(NKW  + 255) / 256, 256>>>(wv, wqkv + (size_t)(DIM + NKV * HD) * GK, NKW);
    prep_f16_1<<<(NBIG + 255) / 256, 256>>>(wo, wop, NBIG);

    cudaFuncSetAttribute(gemm_f16x2,
                         cudaFuncAttributeMaxDynamicSharedMemorySize, GEMM_SMEM);

    // fused qkv projection: one GEMM, N = 5120
    gemm_f16x2<<<dim3(NQKV / 128, MTOK / 128), 256, GEMM_SMEM>>>(xh, xl, wqkv, qkv, NQKV);

    {
        int total = NQP + NKP + NVE;
        rope_pack<<<(total + 255) / 256, 256>>>(fc, fs);
    }

    cudaFuncSetAttribute(flash_hmma,
                         cudaFuncAttributeMaxDynamicSharedMemorySize, FSMEM);
    flash_hmma<<<dim3(TT / 128, NH, BB), 256, FSMEM>>>(fqh, fql, fkh, fkl, fv, ch, cl);

    gemm_f16x2<<<dim3(DIM / 128, MTOK / 128), 256, GEMM_SMEM>>>(ch, cl, wop, out, DIM);
}